// round 11
// baseline (speedup 1.0000x reference)
#include <cuda_runtime.h>
#include <math.h>
#include <cstdint>

// ---------------- problem constants ----------------
#define BB     8      // batch
#define NE     4      // n_equi
#define TT     1024   // T
#define DD     1024   // D_eq
#define GG     8      // N_GROUP
#define BL     128    // BLOCKS
#define SS     64     // T_text
#define DL     2048   // d_llm
#define SCALE  0.08838834764831843f   // 128^-0.5

#define TOK    16     // tokens per block
#define NCH    32     // kv split chunks
#define KC     64     // d_llm per chunk

// ---------------- scratch (device globals; no allocs allowed) ----------------
__device__ float g_kp[NCH * BB * SS * BL];
__device__ float g_vp[NCH * BB * SS * BL];
__device__ float g_k [BB * SS * BL];
__device__ float g_v [BB * SS * BL];

// per-token modulation buffers [b][n][t][128]
__device__ float g_gam [BB * NE * TT * BL];
__device__ float g_bet [BB * NE * TT * BL];
__device__ float g_gate[BB * NE * TT * BL];

// fragment-ordered weights (pre-tf32). wq/wg/wb: [wid 16][kk 16][lane 32]
// we: [oc 4][k 16][ntp 2][lane 32] (uint4 packs 2 n-tiles)
__device__ uint2 g_wqf[16 * 16 * 32];
__device__ uint2 g_wgf[16 * 16 * 32];
__device__ uint2 g_wbf[16 * 16 * 32];
__device__ uint4 g_wef[4 * 16 * 2 * 32];

__device__ __forceinline__ uint32_t f2tf32(float x) {
    uint32_t r; asm("cvt.rna.tf32.f32 %0, %1;" : "=r"(r) : "f"(x)); return r;
}

__device__ __forceinline__ void mma_tf32(float d[4], const uint32_t a[4],
                                         const uint32_t b[2]) {
    asm volatile(
        "mma.sync.aligned.m16n8k8.row.col.f32.tf32.tf32.f32 "
        "{%0,%1,%2,%3}, {%4,%5,%6,%7}, {%8,%9}, {%0,%1,%2,%3};"
        : "+f"(d[0]), "+f"(d[1]), "+f"(d[2]), "+f"(d[3])
        : "r"(a[0]), "r"(a[1]), "r"(a[2]), "r"(a[3]),
          "r"(b[0]), "r"(b[1]));
}

// ================= kernel 0: fragment prep =================
__global__ void frag_prep_kernel(const float* __restrict__ Wq,
                                 const float* __restrict__ Wg,
                                 const float* __restrict__ Wb,
                                 const float* __restrict__ We) {
    int idx = blockIdx.x * 256 + threadIdx.x;
    if (idx < 8192) {
        int lane = idx & 31, kk = (idx >> 5) & 15, w = idx >> 9;
        int lr = lane >> 2, lc = lane & 3;
        int ofs = (w * 8 + lr) * 128 + kk * 8 + lc;
        g_wqf[idx] = make_uint2(f2tf32(Wq[ofs]), f2tf32(Wq[ofs + 4]));
        g_wgf[idx] = make_uint2(f2tf32(Wg[ofs]), f2tf32(Wg[ofs + 4]));
        g_wbf[idx] = make_uint2(f2tf32(Wb[ofs]), f2tf32(Wb[ofs + 4]));
    } else if (idx < 8192 + 4096) {
        int j = idx - 8192;
        int lane = j & 31, ntp = (j >> 5) & 1, k = (j >> 6) & 15, oc = j >> 10;
        int lr = lane >> 2, lc = lane & 3;
        int r0 = (oc * 32 + ntp * 16 + lr) * 128 + k * 8 + lc;
        int r1 = r0 + 8 * 128;
        g_wef[j] = make_uint4(f2tf32(We[r0]), f2tf32(We[r0 + 4]),
                              f2tf32(We[r1]), f2tf32(We[r1 + 4]));
    }
}

// ================= kernel 1: k/v projection, 32 chunks =================
#define K1_SMEM_F (SS * KC + 2 * KC * 129)
__global__ __launch_bounds__(512, 2)
void kv_partial_kernel(const float* __restrict__ h_llm,
                       const float* __restrict__ Wk,
                       const float* __restrict__ Wv) {
    extern __shared__ float sm[];
    float* hs  = sm;
    float* wkT = sm + SS * KC;
    float* wvT = wkT + KC * 129;

    const int dc  = blockIdx.x;
    const int b   = blockIdx.y;
    const int tid = threadIdx.x;

    for (int e = tid; e < SS * (KC / 4); e += 512) {
        int s = e >> 4, d4 = e & 15;
        *reinterpret_cast<float4*>(&hs[s * KC + d4 * 4]) =
            *reinterpret_cast<const float4*>(&h_llm[(b * SS + s) * DL + dc * KC + d4 * 4]);
    }
    for (int e = tid; e < BL * (KC / 4); e += 512) {
        int d4 = e & 15, o = e >> 4;
        float4 wk = *reinterpret_cast<const float4*>(&Wk[o * DL + dc * KC + d4 * 4]);
        float4 wv = *reinterpret_cast<const float4*>(&Wv[o * DL + dc * KC + d4 * 4]);
        int d0 = d4 * 4;
        wkT[(d0 + 0) * 129 + o] = wk.x; wkT[(d0 + 1) * 129 + o] = wk.y;
        wkT[(d0 + 2) * 129 + o] = wk.z; wkT[(d0 + 3) * 129 + o] = wk.w;
        wvT[(d0 + 0) * 129 + o] = wv.x; wvT[(d0 + 1) * 129 + o] = wv.y;
        wvT[(d0 + 2) * 129 + o] = wv.z; wvT[(d0 + 3) * 129 + o] = wv.w;
    }
    __syncthreads();

    const int o = tid & 127, qi = tid >> 7;
    for (int st = 0; st < 4; st++) {
        int s0 = qi * 16 + st * 4;
        float ak[4] = {0.f, 0.f, 0.f, 0.f};
        float av[4] = {0.f, 0.f, 0.f, 0.f};
#pragma unroll 4
        for (int d4 = 0; d4 < KC / 4; d4++) {
            float4 h0 = *reinterpret_cast<const float4*>(&hs[(s0 + 0) * KC + d4 * 4]);
            float4 h1 = *reinterpret_cast<const float4*>(&hs[(s0 + 1) * KC + d4 * 4]);
            float4 h2 = *reinterpret_cast<const float4*>(&hs[(s0 + 2) * KC + d4 * 4]);
            float4 h3 = *reinterpret_cast<const float4*>(&hs[(s0 + 3) * KC + d4 * 4]);
            const float hh[4][4] = {{h0.x, h0.y, h0.z, h0.w},
                                    {h1.x, h1.y, h1.z, h1.w},
                                    {h2.x, h2.y, h2.z, h2.w},
                                    {h3.x, h3.y, h3.z, h3.w}};
#pragma unroll
            for (int jd = 0; jd < 4; jd++) {
                float wk = wkT[(d4 * 4 + jd) * 129 + o];
                float wv = wvT[(d4 * 4 + jd) * 129 + o];
#pragma unroll
                for (int j = 0; j < 4; j++) {
                    ak[j] = fmaf(hh[j][jd], wk, ak[j]);
                    av[j] = fmaf(hh[j][jd], wv, av[j]);
                }
            }
        }
#pragma unroll
        for (int j = 0; j < 4; j++) {
            int oidx = ((dc * BB + b) * SS + s0 + j) * BL + o;
            g_kp[oidx] = ak[j];
            g_vp[oidx] = av[j];
        }
    }
}

// ================= kernel 1b: reduce partials + bias =================
__global__ void kv_reduce_kernel(const float* __restrict__ bk,
                                 const float* __restrict__ bv) {
    int idx = blockIdx.x * 256 + threadIdx.x;
    int o = idx & 127;
    float sk = bk[o], sv = bv[o];
#pragma unroll
    for (int dc = 0; dc < NCH; dc++) {
        sk += g_kp[dc * (BB * SS * BL) + idx];
        sv += g_vp[dc * (BB * SS * BL) + idx];
    }
    g_k[idx] = sk;
    g_v[idx] = sv;
}

// ================= kernel 2: ctx pipeline (gamma/beta/gate) ============
// grid (T/16, n_equi, B), 512 threads, 2 CTA/SM.
#define A_OF_K   0                        // k[s][d] stride 132 : 8448 (tf32 bits)
#define A_OF_V   8448                     // v[s][d] stride 136 : 8704 (tf32 bits)
#define A_OF_INV (8448 + 8704)            // INV[m][i] stride 144 : 2304 (tf32 bits)
#define A_OF_AT  (A_OF_INV + 2304)        // AT[d][m] stride 24 : 3072 (tf32 bits)
#define A_OF_Q   (A_OF_AT + 3072)         // Q[m][o] stride 132 : 2112 (q tf32)
#define A_OF_U   (A_OF_Q + 2112)          // U[m][*] stride 132 : 2112
#define KA_SMEM_F (A_OF_U + 2112)         // 26752 floats = 107008 bytes

__global__ __launch_bounds__(512, 2)
void ctx_kernel(const float* __restrict__ h_prime,
                const float* __restrict__ bq,
                const float* __restrict__ bg,
                const float* __restrict__ bb) {
    extern __shared__ float sm[];
    float* ksm = sm + A_OF_K;
    float* vsm = sm + A_OF_V;
    float* INV = sm + A_OF_INV;   // [m*144 + i] tf32 bits
    float* AT  = sm + A_OF_AT;    // [d*24 + m] tf32 bits (ctx)
    float* Q   = sm + A_OF_Q;
    float* U   = sm + A_OF_U;

    const int tid = threadIdx.x;
    const int wid = tid >> 5;
    const int l   = tid & 31;
    const int lr  = l >> 2;
    const int lc  = l & 3;
    const int t0  = blockIdx.x * TOK;
    const int n   = blockIdx.y;
    const int b   = blockIdx.z;
    const long long base = ((long long)(b * NE + n) * TT + t0) * DD;
    const int baset = ((b * NE + n) * TT + t0) * BL;

    // ---- stage k/v (tf32 bits) ----
#pragma unroll
    for (int k = 0; k < 4; k++) {
        int e = tid + k * 512;
        int s = e >> 5, d4 = e & 31;
        float4 kv4 = *reinterpret_cast<const float4*>(&g_k[(b * SS + s) * BL + d4 * 4]);
        float4 vv4 = *reinterpret_cast<const float4*>(&g_v[(b * SS + s) * BL + d4 * 4]);
        float4 kt, vt;
        kt.x = __uint_as_float(f2tf32(kv4.x)); kt.y = __uint_as_float(f2tf32(kv4.y));
        kt.z = __uint_as_float(f2tf32(kv4.z)); kt.w = __uint_as_float(f2tf32(kv4.w));
        vt.x = __uint_as_float(f2tf32(vv4.x)); vt.y = __uint_as_float(f2tf32(vv4.y));
        vt.z = __uint_as_float(f2tf32(vv4.z)); vt.w = __uint_as_float(f2tf32(vv4.w));
        *reinterpret_cast<float4*>(&ksm[s * 132 + d4 * 4]) = kt;
        *reinterpret_cast<float4*>(&vsm[s * 136 + d4 * 4]) = vt;
    }

    // ---- phase B: group max streamed from gmem (warp = token row) ----
    {
        const int m = wid;
        const float* hrow = h_prime + base + m * DD;
        float4 mx = *reinterpret_cast<const float4*>(&hrow[l * 4]);
#pragma unroll
        for (int g = 1; g < GG; g++) {
            float4 v4 = *reinterpret_cast<const float4*>(&hrow[g * 128 + l * 4]);
            mx.x = fmaxf(mx.x, v4.x); mx.y = fmaxf(mx.y, v4.y);
            mx.z = fmaxf(mx.z, v4.z); mx.w = fmaxf(mx.w, v4.w);
        }
        float4 t;
        t.x = __uint_as_float(f2tf32(mx.x));
        t.y = __uint_as_float(f2tf32(mx.y));
        t.z = __uint_as_float(f2tf32(mx.z));
        t.w = __uint_as_float(f2tf32(mx.w));
        *reinterpret_cast<float4*>(&INV[m * 144 + l * 4]) = t;
    }
    __syncthreads();

    // ---- phase C: q = inv @ WqT + bq (mma) -> Q[m][o] (tf32 bits) ----
    {
        const int o8 = wid * 8;
        float d[4] = {0.f, 0.f, 0.f, 0.f};
#pragma unroll 4
        for (int kk = 0; kk < 16; kk++) {
            const int i0 = kk * 8;
            uint32_t a[4], bf[2];
            a[0] = __float_as_uint(INV[lr * 144 + i0 + lc]);
            a[1] = __float_as_uint(INV[(lr + 8) * 144 + i0 + lc]);
            a[2] = __float_as_uint(INV[lr * 144 + i0 + lc + 4]);
            a[3] = __float_as_uint(INV[(lr + 8) * 144 + i0 + lc + 4]);
            uint2 w2 = g_wqf[(wid * 16 + kk) * 32 + l];
            bf[0] = w2.x; bf[1] = w2.y;
            mma_tf32(d, a, bf);
        }
        float2 bv2 = *reinterpret_cast<const float2*>(&bq[o8 + lc * 2]);
        Q[lr * 132 + o8 + lc * 2]           = __uint_as_float(f2tf32(d[0] + bv2.x));
        Q[lr * 132 + o8 + lc * 2 + 1]       = __uint_as_float(f2tf32(d[1] + bv2.y));
        Q[(lr + 8) * 132 + o8 + lc * 2]     = __uint_as_float(f2tf32(d[2] + bv2.x));
        Q[(lr + 8) * 132 + o8 + lc * 2 + 1] = __uint_as_float(f2tf32(d[3] + bv2.y));
    }
    __syncthreads();

    // ---- phase D: scores = q.k * SCALE (mma, 8 warps) -> U fp32 ----
    if (wid < 8) {
        const int s8 = wid * 8;
        float d[4] = {0.f, 0.f, 0.f, 0.f};
#pragma unroll 4
        for (int kk = 0; kk < 16; kk++) {
            const int i0 = kk * 8;
            uint32_t a[4], bf[2];
            a[0] = __float_as_uint(Q[lr * 132 + i0 + lc]);
            a[1] = __float_as_uint(Q[(lr + 8) * 132 + i0 + lc]);
            a[2] = __float_as_uint(Q[lr * 132 + i0 + lc + 4]);
            a[3] = __float_as_uint(Q[(lr + 8) * 132 + i0 + lc + 4]);
            bf[0] = __float_as_uint(ksm[(s8 + lr) * 132 + i0 + lc]);
            bf[1] = __float_as_uint(ksm[(s8 + lr) * 132 + i0 + lc + 4]);
            mma_tf32(d, a, bf);
        }
        U[lr * 132 + s8 + lc * 2]           = d[0] * SCALE;
        U[lr * 132 + s8 + lc * 2 + 1]       = d[1] * SCALE;
        U[(lr + 8) * 132 + s8 + lc * 2]     = d[2] * SCALE;
        U[(lr + 8) * 132 + s8 + lc * 2 + 1] = d[3] * SCALE;
    }
    __syncthreads();

    // ---- phase E: softmax, one warp per row -> U probs (tf32 bits) ----
    {
        float x0 = U[wid * 132 + l];
        float x1 = U[wid * 132 + l + 32];
        float mx = fmaxf(x0, x1);
#pragma unroll
        for (int off = 16; off > 0; off >>= 1)
            mx = fmaxf(mx, __shfl_xor_sync(0xffffffffu, mx, off));
        float e0 = __expf(x0 - mx), e1 = __expf(x1 - mx);
        float s = e0 + e1;
#pragma unroll
        for (int off = 16; off > 0; off >>= 1)
            s += __shfl_xor_sync(0xffffffffu, s, off);
        float inv = 1.f / s;
        U[wid * 132 + l]      = __uint_as_float(f2tf32(e0 * inv));
        U[wid * 132 + l + 32] = __uint_as_float(f2tf32(e1 * inv));
    }
    __syncthreads();

    // ---- phase F: ctx = attn @ v (mma) -> AT tf32 ; gate -> gmem ----
    {
        const int o8 = wid * 8;
        float d[4] = {0.f, 0.f, 0.f, 0.f};
#pragma unroll 4
        for (int kk = 0; kk < 8; kk++) {
            const int i0 = kk * 8;
            uint32_t a[4], bf[2];
            a[0] = __float_as_uint(U[lr * 132 + i0 + lc]);
            a[1] = __float_as_uint(U[(lr + 8) * 132 + i0 + lc]);
            a[2] = __float_as_uint(U[lr * 132 + i0 + lc + 4]);
            a[3] = __float_as_uint(U[(lr + 8) * 132 + i0 + lc + 4]);
            bf[0] = __float_as_uint(vsm[(i0 + lc) * 136 + o8 + lr]);
            bf[1] = __float_as_uint(vsm[(i0 + lc + 4) * 136 + o8 + lr]);
            mma_tf32(d, a, bf);
        }
        AT[(o8 + lc * 2) * 24 + lr]         = __uint_as_float(f2tf32(d[0]));
        AT[(o8 + lc * 2 + 1) * 24 + lr]     = __uint_as_float(f2tf32(d[1]));
        AT[(o8 + lc * 2) * 24 + lr + 8]     = __uint_as_float(f2tf32(d[2]));
        AT[(o8 + lc * 2 + 1) * 24 + lr + 8] = __uint_as_float(f2tf32(d[3]));
        float2 glo, ghi;
        glo.x = 1.f / (1.f + __expf(-d[0]));
        glo.y = 1.f / (1.f + __expf(-d[1]));
        ghi.x = 1.f / (1.f + __expf(-d[2]));
        ghi.y = 1.f / (1.f + __expf(-d[3]));
        *reinterpret_cast<float2*>(&g_gate[baset + lr * BL + o8 + lc * 2])       = glo;
        *reinterpret_cast<float2*>(&g_gate[baset + (lr + 8) * BL + o8 + lc * 2]) = ghi;
    }
    __syncthreads();

    // ---- phase G: gamma & beta (merged mma) -> gmem ----
    {
        const int o8 = wid * 8;
        float dg[4] = {0.f, 0.f, 0.f, 0.f};
        float db[4] = {0.f, 0.f, 0.f, 0.f};
#pragma unroll 4
        for (int kk = 0; kk < 16; kk++) {
            const int i0 = kk * 8;
            uint32_t a[4], bG[2], bB[2];
            a[0] = __float_as_uint(AT[(i0 + lc) * 24 + lr]);
            a[1] = __float_as_uint(AT[(i0 + lc) * 24 + lr + 8]);
            a[2] = __float_as_uint(AT[(i0 + lc + 4) * 24 + lr]);
            a[3] = __float_as_uint(AT[(i0 + lc + 4) * 24 + lr + 8]);
            uint2 wg2 = g_wgf[(wid * 16 + kk) * 32 + l];
            uint2 wb2 = g_wbf[(wid * 16 + kk) * 32 + l];
            bG[0] = wg2.x; bG[1] = wg2.y;
            bB[0] = wb2.x; bB[1] = wb2.y;
            mma_tf32(dg, a, bG);
            mma_tf32(db, a, bB);
        }
        float2 bgv = *reinterpret_cast<const float2*>(&bg[o8 + lc * 2]);
        float2 bbv = *reinterpret_cast<const float2*>(&bb[o8 + lc * 2]);
        float2 w0, w1;
        w0.x = dg[0] + bgv.x; w0.y = dg[1] + bgv.y;
        w1.x = dg[2] + bgv.x; w1.y = dg[3] + bgv.y;
        *reinterpret_cast<float2*>(&g_gam[baset + lr * BL + o8 + lc * 2])       = w0;
        *reinterpret_cast<float2*>(&g_gam[baset + (lr + 8) * BL + o8 + lc * 2]) = w1;
        w0.x = db[0] + bbv.x; w0.y = db[1] + bbv.y;
        w1.x = db[2] + bbv.x; w1.y = db[3] + bbv.y;
        *reinterpret_cast<float2*>(&g_bet[baset + lr * BL + o8 + lc * 2])       = w0;
        *reinterpret_cast<float2*>(&g_bet[baset + (lr + 8) * BL + o8 + lc * 2]) = w1;
    }
}

// ================= kernel 3: equi GEMM + epilogue =================
// grid (T/16, n_equi, B), 512 threads, 2 CTA/SM.
#define HS     1036                       // H row stride (1036 mod 32 == 12)
#define B_OF_H   0                        // H[m][d] : 16576
#define B_OF_GAM 16576                    // [m][o] stride 132 : 2112
#define B_OF_BET (B_OF_GAM + 2112)
#define B_OF_GAT (B_OF_BET + 2112)
#define KB_SMEM_F (B_OF_GAT + 2112)       // 22912 floats = 91648 bytes

__global__ __launch_bounds__(512, 2)
void equi_kernel(const float* __restrict__ h_prime,
                 float* __restrict__ out) {
    extern __shared__ float sm[];
    float* H   = sm + B_OF_H;
    float* GAM = sm + B_OF_GAM;
    float* BET = sm + B_OF_BET;
    float* GAT = sm + B_OF_GAT;

    const int tid = threadIdx.x;
    const int wid = tid >> 5;
    const int l   = tid & 31;
    const int lr  = l >> 2;
    const int lc  = l & 3;
    const int t0  = blockIdx.x * TOK;
    const int n   = blockIdx.y;
    const int b   = blockIdx.z;
    const long long base = ((long long)(b * NE + n) * TT + t0) * DD;
    const int baset = ((b * NE + n) * TT + t0) * BL;

    // ---- phase A: load H + stage gamma/beta/gate ----
#pragma unroll
    for (int k = 0; k < 8; k++) {
        int e = tid + k * 512;                 // 4096 float4
        int m = e >> 8, c4 = e & 255;
        *reinterpret_cast<float4*>(&H[m * HS + c4 * 4]) =
            *reinterpret_cast<const float4*>(&h_prime[base + m * DD + c4 * 4]);
    }
    {
        int m = tid >> 5, c4 = tid & 31;       // 512 threads = 16x32
        int gi = baset + m * BL + c4 * 4;
        *reinterpret_cast<float4*>(&GAM[m * 132 + c4 * 4]) =
            *reinterpret_cast<const float4*>(&g_gam[gi]);
        *reinterpret_cast<float4*>(&BET[m * 132 + c4 * 4]) =
            *reinterpret_cast<const float4*>(&g_bet[gi]);
        *reinterpret_cast<float4*>(&GAT[m * 132 + c4 * 4]) =
            *reinterpret_cast<const float4*>(&g_gate[gi]);
    }
    __syncthreads();

    // ---- phase J: equi GEMM (mma, frag We) + epilogue ----
    {
        const int r0 = (wid >> 2) * 32;
        const int oc = wid & 3;
        const int o0 = oc * 32;
        const int g0 = r0 >> 4;

        float d[2][4][4];
#pragma unroll
        for (int mt = 0; mt < 2; mt++)
#pragma unroll
            for (int nt = 0; nt < 4; nt++)
#pragma unroll
                for (int j = 0; j < 4; j++) d[mt][nt][j] = 0.f;

#pragma unroll 2
        for (int k = 0; k < 16; k++) {
            const int i0 = k * 8;
            uint32_t a[2][4], bfr[4][2];
#pragma unroll
            for (int mt = 0; mt < 2; mt++) {
                const float* Alo = &H[lr * HS + (g0 + mt) * 128 + i0 + lc];
                const float* Ahi = &H[(lr + 8) * HS + (g0 + mt) * 128 + i0 + lc];
                a[mt][0] = f2tf32(Alo[0]);
                a[mt][1] = f2tf32(Ahi[0]);
                a[mt][2] = f2tf32(Alo[4]);
                a[mt][3] = f2tf32(Ahi[4]);
            }
            uint4 b01 = g_wef[((oc * 16 + k) * 2 + 0) * 32 + l];
            uint4 b23 = g_wef[((oc * 16 + k) * 2 + 1) * 32 + l];
            bfr[0][0] = b01.x; bfr[0][1] = b01.y;
            bfr[1][0] = b01.z; bfr[1][1] = b01.w;
            bfr[2][0] = b23.x; bfr[2][1] = b23.y;
            bfr[3][0] = b23.z; bfr[3][1] = b23.w;
#pragma unroll
            for (int mt = 0; mt < 2; mt++)
#pragma unroll
                for (int nt = 0; nt < 4; nt++)
                    mma_tf32(d[mt][nt], a[mt], bfr[nt]);
        }

#pragma unroll
        for (int mt = 0; mt < 2; mt++) {
#pragma unroll
            for (int rh = 0; rh < 2; rh++) {
                const int m = lr + rh * 8;
                const int g = g0 + mt;
                float* orow = out + base + m * DD + g * 128;
                const float* hrow = &H[m * HS + g * 128];
#pragma unroll
                for (int nt = 0; nt < 4; nt++) {
                    const int o = o0 + nt * 8 + lc * 2;
                    float e0 = d[mt][nt][rh * 2 + 0];
                    float e1 = d[mt][nt][rh * 2 + 1];
                    float2 gam = *reinterpret_cast<const float2*>(&GAM[m * 132 + o]);
                    float2 bet = *reinterpret_cast<const float2*>(&BET[m * 132 + o]);
                    float2 gat = *reinterpret_cast<const float2*>(&GAT[m * 132 + o]);
                    float2 res = *reinterpret_cast<const float2*>(&hrow[o]);
                    float2 ov;
                    ov.x = res.x + gat.x * (gam.x * e0 + bet.x);
                    ov.y = res.y + gat.y * (gam.y * e1 + bet.y);
                    *reinterpret_cast<float2*>(&orow[o]) = ov;
                }
            }
        }
    }
}

// ================= launcher =================
extern "C" void kernel_launch(void* const* d_in, const int* in_sizes, int n_in,
                              void* d_out, int out_size) {
    const float* h_prime = (const float*)d_in[0];
    const float* h_llm   = (const float*)d_in[1];
    const float* Wq = (const float*)d_in[2];
    const float* bq = (const float*)d_in[3];
    const float* Wk = (const float*)d_in[4];
    const float* bk = (const float*)d_in[5];
    const float* Wv = (const float*)d_in[6];
    const float* bv = (const float*)d_in[7];
    const float* Wg = (const float*)d_in[8];
    const float* bg = (const float*)d_in[9];
    const float* Wb = (const float*)d_in[10];
    const float* bb = (const float*)d_in[11];
    const float* We = (const float*)d_in[12];
    float* out = (float*)d_out;

    (void)in_sizes; (void)n_in; (void)out_size;

    size_t sm1 = K1_SMEM_F * sizeof(float);
    size_t smA = KA_SMEM_F * sizeof(float);
    size_t smB = KB_SMEM_F * sizeof(float);
    cudaFuncSetAttribute(kv_partial_kernel,
                         cudaFuncAttributeMaxDynamicSharedMemorySize, (int)sm1);
    cudaFuncSetAttribute(ctx_kernel,
                         cudaFuncAttributeMaxDynamicSharedMemorySize, (int)smA);
    cudaFuncSetAttribute(equi_kernel,
                         cudaFuncAttributeMaxDynamicSharedMemorySize, (int)smB);

    frag_prep_kernel<<<48, 256>>>(Wq, Wg, Wb, We);
    kv_partial_kernel<<<dim3(NCH, BB), 512, sm1>>>(h_llm, Wk, Wv);
    kv_reduce_kernel<<<(BB * SS * BL) / 256, 256>>>(bk, bv);
    ctx_kernel<<<dim3(TT / TOK, NE, BB), 512, smA>>>(h_prime, bq, bg, bb);
    equi_kernel<<<dim3(TT / TOK, NE, BB), 512, smB>>>(h_prime, out);
}

// round 12
// speedup vs baseline: 1.2797x; 1.2797x over previous
#include <cuda_runtime.h>
#include <math.h>
#include <cstdint>

// ---------------- problem constants ----------------
#define BB     8      // batch
#define NE     4      // n_equi
#define TT     1024   // T
#define DD     1024   // D_eq
#define GG     8      // N_GROUP
#define BL     128    // BLOCKS
#define SS     64     // T_text
#define DL     2048   // d_llm
#define SCALE  0.08838834764831843f   // 128^-0.5

#define TOK    16     // tokens per block
#define NCH    32     // kv split chunks
#define KC     64     // d_llm per chunk

// ---------------- scratch (device globals; no allocs allowed) ----------------
__device__ float g_kp[NCH * BB * SS * BL];
__device__ float g_vp[NCH * BB * SS * BL];

// fragment-ordered k/v (pre-tf32 bits).
// g_kf: [b][s_warp 8][kk 16][lane 32] uint2   (scores B operand)
// g_vf: [b][d_warp 16][kk 8][lane 32] uint2   (ctx B operand)
__device__ uint2 g_kf[BB * 8 * 16 * 32];
__device__ uint2 g_vf[BB * 16 * 8 * 32];

// fragment-ordered weights (pre-tf32). wq/wg/wb: [wid 16][kk 16][lane 32]
// we: [oc 4][k 16][ntp 2][lane 32] (uint4 packs 2 n-tiles)
__device__ uint2 g_wqf[16 * 16 * 32];
__device__ uint2 g_wgf[16 * 16 * 32];
__device__ uint2 g_wbf[16 * 16 * 32];
__device__ uint4 g_wef[4 * 16 * 2 * 32];

__device__ __forceinline__ uint32_t f2tf32(float x) {
    uint32_t r; asm("cvt.rna.tf32.f32 %0, %1;" : "=r"(r) : "f"(x)); return r;
}

__device__ __forceinline__ void mma_tf32(float d[4], const uint32_t a[4],
                                         const uint32_t b[2]) {
    asm volatile(
        "mma.sync.aligned.m16n8k8.row.col.f32.tf32.tf32.f32 "
        "{%0,%1,%2,%3}, {%4,%5,%6,%7}, {%8,%9}, {%0,%1,%2,%3};"
        : "+f"(d[0]), "+f"(d[1]), "+f"(d[2]), "+f"(d[3])
        : "r"(a[0]), "r"(a[1]), "r"(a[2]), "r"(a[3]),
          "r"(b[0]), "r"(b[1]));
}

// ================= kernel 0: fragment prep =================
__global__ void frag_prep_kernel(const float* __restrict__ Wq,
                                 const float* __restrict__ Wg,
                                 const float* __restrict__ Wb,
                                 const float* __restrict__ We) {
    int idx = blockIdx.x * 256 + threadIdx.x;
    if (idx < 8192) {
        int lane = idx & 31, kk = (idx >> 5) & 15, w = idx >> 9;
        int lr = lane >> 2, lc = lane & 3;
        int ofs = (w * 8 + lr) * 128 + kk * 8 + lc;
        g_wqf[idx] = make_uint2(f2tf32(Wq[ofs]), f2tf32(Wq[ofs + 4]));
        g_wgf[idx] = make_uint2(f2tf32(Wg[ofs]), f2tf32(Wg[ofs + 4]));
        g_wbf[idx] = make_uint2(f2tf32(Wb[ofs]), f2tf32(Wb[ofs + 4]));
    } else if (idx < 8192 + 4096) {
        int j = idx - 8192;
        int lane = j & 31, ntp = (j >> 5) & 1, k = (j >> 6) & 15, oc = j >> 10;
        int lr = lane >> 2, lc = lane & 3;
        int r0 = (oc * 32 + ntp * 16 + lr) * 128 + k * 8 + lc;
        int r1 = r0 + 8 * 128;
        g_wef[j] = make_uint4(f2tf32(We[r0]), f2tf32(We[r0 + 4]),
                              f2tf32(We[r1]), f2tf32(We[r1 + 4]));
    }
}

// ================= kernel 1: k/v projection, 32 chunks =================
#define K1_SMEM_F (SS * KC + 2 * KC * 129)
__global__ __launch_bounds__(512, 2)
void kv_partial_kernel(const float* __restrict__ h_llm,
                       const float* __restrict__ Wk,
                       const float* __restrict__ Wv) {
    extern __shared__ float sm[];
    float* hs  = sm;
    float* wkT = sm + SS * KC;
    float* wvT = wkT + KC * 129;

    const int dc  = blockIdx.x;
    const int b   = blockIdx.y;
    const int tid = threadIdx.x;

    for (int e = tid; e < SS * (KC / 4); e += 512) {
        int s = e >> 4, d4 = e & 15;
        *reinterpret_cast<float4*>(&hs[s * KC + d4 * 4]) =
            *reinterpret_cast<const float4*>(&h_llm[(b * SS + s) * DL + dc * KC + d4 * 4]);
    }
    for (int e = tid; e < BL * (KC / 4); e += 512) {
        int d4 = e & 15, o = e >> 4;
        float4 wk = *reinterpret_cast<const float4*>(&Wk[o * DL + dc * KC + d4 * 4]);
        float4 wv = *reinterpret_cast<const float4*>(&Wv[o * DL + dc * KC + d4 * 4]);
        int d0 = d4 * 4;
        wkT[(d0 + 0) * 129 + o] = wk.x; wkT[(d0 + 1) * 129 + o] = wk.y;
        wkT[(d0 + 2) * 129 + o] = wk.z; wkT[(d0 + 3) * 129 + o] = wk.w;
        wvT[(d0 + 0) * 129 + o] = wv.x; wvT[(d0 + 1) * 129 + o] = wv.y;
        wvT[(d0 + 2) * 129 + o] = wv.z; wvT[(d0 + 3) * 129 + o] = wv.w;
    }
    __syncthreads();

    const int o = tid & 127, qi = tid >> 7;
    for (int st = 0; st < 4; st++) {
        int s0 = qi * 16 + st * 4;
        float ak[4] = {0.f, 0.f, 0.f, 0.f};
        float av[4] = {0.f, 0.f, 0.f, 0.f};
#pragma unroll 4
        for (int d4 = 0; d4 < KC / 4; d4++) {
            float4 h0 = *reinterpret_cast<const float4*>(&hs[(s0 + 0) * KC + d4 * 4]);
            float4 h1 = *reinterpret_cast<const float4*>(&hs[(s0 + 1) * KC + d4 * 4]);
            float4 h2 = *reinterpret_cast<const float4*>(&hs[(s0 + 2) * KC + d4 * 4]);
            float4 h3 = *reinterpret_cast<const float4*>(&hs[(s0 + 3) * KC + d4 * 4]);
            const float hh[4][4] = {{h0.x, h0.y, h0.z, h0.w},
                                    {h1.x, h1.y, h1.z, h1.w},
                                    {h2.x, h2.y, h2.z, h2.w},
                                    {h3.x, h3.y, h3.z, h3.w}};
#pragma unroll
            for (int jd = 0; jd < 4; jd++) {
                float wk = wkT[(d4 * 4 + jd) * 129 + o];
                float wv = wvT[(d4 * 4 + jd) * 129 + o];
#pragma unroll
                for (int j = 0; j < 4; j++) {
                    ak[j] = fmaf(hh[j][jd], wk, ak[j]);
                    av[j] = fmaf(hh[j][jd], wv, av[j]);
                }
            }
        }
#pragma unroll
        for (int j = 0; j < 4; j++) {
            int oidx = ((dc * BB + b) * SS + s0 + j) * BL + o;
            g_kp[oidx] = ak[j];
            g_vp[oidx] = av[j];
        }
    }
}

// ====== kernel 1b: reduce partials + bias -> fragment-ordered k/v ======
__global__ void kv_reduce_kernel(const float* __restrict__ bk,
                                 const float* __restrict__ bv) {
    int idx = blockIdx.x * 256 + threadIdx.x;     // [b][s][o]
    int o = idx & 127;
    int s = (idx >> 7) & 63;
    int b = idx >> 13;
    float sk = bk[o], sv = bv[o];
#pragma unroll
    for (int dc = 0; dc < NCH; dc++) {
        sk += g_kp[dc * (BB * SS * BL) + idx];
        sv += g_vp[dc * (BB * SS * BL) + idx];
    }
    // k fragment: n = s, kdim = o
    int pos_k = ((b * 8 + (s >> 3)) * 16 + (o >> 3)) * 32 + (s & 7) * 4 + (o & 3);
    reinterpret_cast<uint32_t*>(g_kf)[pos_k * 2 + ((o >> 2) & 1)] = f2tf32(sk);
    // v fragment: n = o (d), kdim = s
    int pos_v = ((b * 16 + (o >> 3)) * 8 + (s >> 3)) * 32 + (o & 7) * 4 + (s & 3);
    reinterpret_cast<uint32_t*>(g_vf)[pos_v * 2 + ((s >> 2) & 1)] = f2tf32(sv);
}

// ================= kernel 2: fused, all-mma, 2 CTA/SM =================
// grid (T/16, n_equi, B), 512 threads.
#define HS     1036                       // H row stride (1036 mod 32 == 12)
#define OF_H   0                          // H[m][d] : 16*1036 = 16576
#define OF_INV 16576                      // INV[m][i] stride 132 : 2112 (tf32 bits)
#define OF_AT  (OF_INV + 2112)            // AT[d][m] stride 24 : 3072 (tf32 bits)
#define OF_Q   (OF_AT + 3072)             // Q[m][o] stride 132 : 2112
#define OF_U   (OF_Q + 2112)              // U[m][*] stride 132 : 2112
#define OF_CT  (OF_U + 2112)              // gate[m][o] stride 132 : 2112
#define K2_SMEM_F (OF_CT + 2112)          // 28096 floats = 112384 bytes

__global__ __launch_bounds__(512, 2)
void fused_kernel(const float* __restrict__ h_prime,
                  const float* __restrict__ bq,
                  const float* __restrict__ bg,
                  const float* __restrict__ bb,
                  float* __restrict__ out) {
    extern __shared__ float sm[];
    float* H   = sm + OF_H;    // [m*1036 + d] fp32
    float* INV = sm + OF_INV;  // [m*132 + i] tf32 bits
    float* AT  = sm + OF_AT;   // [d*24 + m] tf32 bits (ctx)
    float* Q   = sm + OF_Q;    // [m*132 + o]
    float* U   = sm + OF_U;    // [m*132 + *]
    float* CT  = sm + OF_CT;   // [m*132 + o] gate fp32

    const int tid = threadIdx.x;
    const int wid = tid >> 5;
    const int l   = tid & 31;
    const int lr  = l >> 2;
    const int lc  = l & 3;
    const int t0  = blockIdx.x * TOK;
    const int n   = blockIdx.y;
    const int b   = blockIdx.z;
    const long long base = ((long long)(b * NE + n) * TT + t0) * DD;

    // ---- phase A: stream h (warp = token), store H + group-max -> INV ----
    {
        const int m = wid;                 // 0..15
        const float* hrow = h_prime + base + m * DD + l * 4;
        float* Hrow = &H[m * HS + l * 4];
        float4 v0 = *reinterpret_cast<const float4*>(hrow);
        *reinterpret_cast<float4*>(Hrow) = v0;
        float4 mx = v0;
#pragma unroll
        for (int g = 1; g < GG; g++) {
            float4 vg = *reinterpret_cast<const float4*>(hrow + g * 128);
            *reinterpret_cast<float4*>(Hrow + g * 128) = vg;
            mx.x = fmaxf(mx.x, vg.x); mx.y = fmaxf(mx.y, vg.y);
            mx.z = fmaxf(mx.z, vg.z); mx.w = fmaxf(mx.w, vg.w);
        }
        float4 t;
        t.x = __uint_as_float(f2tf32(mx.x));
        t.y = __uint_as_float(f2tf32(mx.y));
        t.z = __uint_as_float(f2tf32(mx.z));
        t.w = __uint_as_float(f2tf32(mx.w));
        *reinterpret_cast<float4*>(&INV[m * 132 + l * 4]) = t;
    }
    __syncthreads();

    // ---- phase C: q = inv @ WqT + bq (mma) -> Q[m][o] (tf32 bits) ----
    {
        const int o8 = wid * 8;
        float d[4] = {0.f, 0.f, 0.f, 0.f};
#pragma unroll 4
        for (int kk = 0; kk < 16; kk++) {
            const int i0 = kk * 8;
            uint32_t a[4], bf[2];
            a[0] = __float_as_uint(INV[lr * 132 + i0 + lc]);
            a[1] = __float_as_uint(INV[(lr + 8) * 132 + i0 + lc]);
            a[2] = __float_as_uint(INV[lr * 132 + i0 + lc + 4]);
            a[3] = __float_as_uint(INV[(lr + 8) * 132 + i0 + lc + 4]);
            uint2 w2 = g_wqf[(wid * 16 + kk) * 32 + l];
            bf[0] = w2.x; bf[1] = w2.y;
            mma_tf32(d, a, bf);
        }
        float2 bv2 = *reinterpret_cast<const float2*>(&bq[o8 + lc * 2]);
        Q[lr * 132 + o8 + lc * 2]           = __uint_as_float(f2tf32(d[0] + bv2.x));
        Q[lr * 132 + o8 + lc * 2 + 1]       = __uint_as_float(f2tf32(d[1] + bv2.y));
        Q[(lr + 8) * 132 + o8 + lc * 2]     = __uint_as_float(f2tf32(d[2] + bv2.x));
        Q[(lr + 8) * 132 + o8 + lc * 2 + 1] = __uint_as_float(f2tf32(d[3] + bv2.y));
    }
    __syncthreads();

    // ---- phase D: scores = q.k * SCALE (mma, 8 warps, k-frags gmem) ----
    if (wid < 8) {
        const int s8 = wid * 8;
        float d[4] = {0.f, 0.f, 0.f, 0.f};
#pragma unroll 4
        for (int kk = 0; kk < 16; kk++) {
            const int i0 = kk * 8;
            uint32_t a[4], bf[2];
            a[0] = __float_as_uint(Q[lr * 132 + i0 + lc]);
            a[1] = __float_as_uint(Q[(lr + 8) * 132 + i0 + lc]);
            a[2] = __float_as_uint(Q[lr * 132 + i0 + lc + 4]);
            a[3] = __float_as_uint(Q[(lr + 8) * 132 + i0 + lc + 4]);
            uint2 k2 = g_kf[((b * 8 + wid) * 16 + kk) * 32 + l];
            bf[0] = k2.x; bf[1] = k2.y;
            mma_tf32(d, a, bf);
        }
        U[lr * 132 + s8 + lc * 2]           = d[0] * SCALE;
        U[lr * 132 + s8 + lc * 2 + 1]       = d[1] * SCALE;
        U[(lr + 8) * 132 + s8 + lc * 2]     = d[2] * SCALE;
        U[(lr + 8) * 132 + s8 + lc * 2 + 1] = d[3] * SCALE;
    }
    __syncthreads();

    // ---- phase E: softmax, one warp per row -> U probs (tf32 bits) ----
    {
        float x0 = U[wid * 132 + l];
        float x1 = U[wid * 132 + l + 32];
        float mx = fmaxf(x0, x1);
#pragma unroll
        for (int off = 16; off > 0; off >>= 1)
            mx = fmaxf(mx, __shfl_xor_sync(0xffffffffu, mx, off));
        float e0 = __expf(x0 - mx), e1 = __expf(x1 - mx);
        float s = e0 + e1;
#pragma unroll
        for (int off = 16; off > 0; off >>= 1)
            s += __shfl_xor_sync(0xffffffffu, s, off);
        float inv = 1.f / s;
        U[wid * 132 + l]      = __uint_as_float(f2tf32(e0 * inv));
        U[wid * 132 + l + 32] = __uint_as_float(f2tf32(e1 * inv));
    }
    __syncthreads();

    // ---- phase F: ctx = attn @ v (mma, v-frags gmem) -> AT tf32 + CT gate ----
    {
        const int o8 = wid * 8;
        float d[4] = {0.f, 0.f, 0.f, 0.f};
#pragma unroll 4
        for (int kk = 0; kk < 8; kk++) {
            const int i0 = kk * 8;
            uint32_t a[4], bf[2];
            a[0] = __float_as_uint(U[lr * 132 + i0 + lc]);
            a[1] = __float_as_uint(U[(lr + 8) * 132 + i0 + lc]);
            a[2] = __float_as_uint(U[lr * 132 + i0 + lc + 4]);
            a[3] = __float_as_uint(U[(lr + 8) * 132 + i0 + lc + 4]);
            uint2 v2 = g_vf[((b * 16 + wid) * 8 + kk) * 32 + l];
            bf[0] = v2.x; bf[1] = v2.y;
            mma_tf32(d, a, bf);
        }
        AT[(o8 + lc * 2) * 24 + lr]         = __uint_as_float(f2tf32(d[0]));
        AT[(o8 + lc * 2 + 1) * 24 + lr]     = __uint_as_float(f2tf32(d[1]));
        AT[(o8 + lc * 2) * 24 + lr + 8]     = __uint_as_float(f2tf32(d[2]));
        AT[(o8 + lc * 2 + 1) * 24 + lr + 8] = __uint_as_float(f2tf32(d[3]));
        CT[lr * 132 + o8 + lc * 2]           = 1.f / (1.f + __expf(-d[0]));
        CT[lr * 132 + o8 + lc * 2 + 1]       = 1.f / (1.f + __expf(-d[1]));
        CT[(lr + 8) * 132 + o8 + lc * 2]     = 1.f / (1.f + __expf(-d[2]));
        CT[(lr + 8) * 132 + o8 + lc * 2 + 1] = 1.f / (1.f + __expf(-d[3]));
    }
    __syncthreads();

    // ---- phase G: gamma & beta (merged mma) -> Q (fp32), U (fp32) ----
    {
        const int o8 = wid * 8;
        float dg[4] = {0.f, 0.f, 0.f, 0.f};
        float db[4] = {0.f, 0.f, 0.f, 0.f};
#pragma unroll 4
        for (int kk = 0; kk < 16; kk++) {
            const int i0 = kk * 8;
            uint32_t a[4], bG[2], bB[2];
            a[0] = __float_as_uint(AT[(i0 + lc) * 24 + lr]);
            a[1] = __float_as_uint(AT[(i0 + lc) * 24 + lr + 8]);
            a[2] = __float_as_uint(AT[(i0 + lc + 4) * 24 + lr]);
            a[3] = __float_as_uint(AT[(i0 + lc + 4) * 24 + lr + 8]);
            uint2 wg2 = g_wgf[(wid * 16 + kk) * 32 + l];
            uint2 wb2 = g_wbf[(wid * 16 + kk) * 32 + l];
            bG[0] = wg2.x; bG[1] = wg2.y;
            bB[0] = wb2.x; bB[1] = wb2.y;
            mma_tf32(dg, a, bG);
            mma_tf32(db, a, bB);
        }
        float2 bgv = *reinterpret_cast<const float2*>(&bg[o8 + lc * 2]);
        float2 bbv = *reinterpret_cast<const float2*>(&bb[o8 + lc * 2]);
        Q[lr * 132 + o8 + lc * 2]           = dg[0] + bgv.x;
        Q[lr * 132 + o8 + lc * 2 + 1]       = dg[1] + bgv.y;
        Q[(lr + 8) * 132 + o8 + lc * 2]     = dg[2] + bgv.x;
        Q[(lr + 8) * 132 + o8 + lc * 2 + 1] = dg[3] + bgv.y;
        U[lr * 132 + o8 + lc * 2]           = db[0] + bbv.x;
        U[lr * 132 + o8 + lc * 2 + 1]       = db[1] + bbv.y;
        U[(lr + 8) * 132 + o8 + lc * 2]     = db[2] + bbv.x;
        U[(lr + 8) * 132 + o8 + lc * 2 + 1] = db[3] + bbv.y;
    }
    __syncthreads();

    // ---- phase J: equi GEMM (mma, frag We) + epilogue ----
    {
        const int r0 = (wid >> 2) * 32;
        const int oc = wid & 3;
        const int o0 = oc * 32;
        const int g0 = r0 >> 4;

        float d[2][4][4];
#pragma unroll
        for (int mt = 0; mt < 2; mt++)
#pragma unroll
            for (int nt = 0; nt < 4; nt++)
#pragma unroll
                for (int j = 0; j < 4; j++) d[mt][nt][j] = 0.f;

#pragma unroll 2
        for (int k = 0; k < 16; k++) {
            const int i0 = k * 8;
            uint32_t a[2][4], bfr[4][2];
#pragma unroll
            for (int mt = 0; mt < 2; mt++) {
                const float* Alo = &H[lr * HS + (g0 + mt) * 128 + i0 + lc];
                const float* Ahi = &H[(lr + 8) * HS + (g0 + mt) * 128 + i0 + lc];
                a[mt][0] = f2tf32(Alo[0]);
                a[mt][1] = f2tf32(Ahi[0]);
                a[mt][2] = f2tf32(Alo[4]);
                a[mt][3] = f2tf32(Ahi[4]);
            }
            uint4 b01 = g_wef[((oc * 16 + k) * 2 + 0) * 32 + l];
            uint4 b23 = g_wef[((oc * 16 + k) * 2 + 1) * 32 + l];
            bfr[0][0] = b01.x; bfr[0][1] = b01.y;
            bfr[1][0] = b01.z; bfr[1][1] = b01.w;
            bfr[2][0] = b23.x; bfr[2][1] = b23.y;
            bfr[3][0] = b23.z; bfr[3][1] = b23.w;
#pragma unroll
            for (int mt = 0; mt < 2; mt++)
#pragma unroll
                for (int nt = 0; nt < 4; nt++)
                    mma_tf32(d[mt][nt], a[mt], bfr[nt]);
        }

#pragma unroll
        for (int mt = 0; mt < 2; mt++) {
#pragma unroll
            for (int rh = 0; rh < 2; rh++) {
                const int m = lr + rh * 8;
                const int g = g0 + mt;
                float* orow = out + base + m * DD + g * 128;
                const float* hrow = &H[m * HS + g * 128];
#pragma unroll
                for (int nt = 0; nt < 4; nt++) {
                    const int o = o0 + nt * 8 + lc * 2;
                    float e0 = d[mt][nt][rh * 2 + 0];
                    float e1 = d[mt][nt][rh * 2 + 1];
                    float2 gam = *reinterpret_cast<const float2*>(&Q[m * 132 + o]);
                    float2 bet = *reinterpret_cast<const float2*>(&U[m * 132 + o]);
                    float2 gat = *reinterpret_cast<const float2*>(&CT[m * 132 + o]);
                    float2 res = *reinterpret_cast<const float2*>(&hrow[o]);
                    float2 ov;
                    ov.x = res.x + gat.x * (gam.x * e0 + bet.x);
                    ov.y = res.y + gat.y * (gam.y * e1 + bet.y);
                    *reinterpret_cast<float2*>(&orow[o]) = ov;
                }
            }
        }
    }
}

// ================= launcher =================
extern "C" void kernel_launch(void* const* d_in, const int* in_sizes, int n_in,
                              void* d_out, int out_size) {
    const float* h_prime = (const float*)d_in[0];
    const float* h_llm   = (const float*)d_in[1];
    const float* Wq = (const float*)d_in[2];
    const float* bq = (const float*)d_in[3];
    const float* Wk = (const float*)d_in[4];
    const float* bk = (const float*)d_in[5];
    const float* Wv = (const float*)d_in[6];
    const float* bv = (const float*)d_in[7];
    const float* Wg = (const float*)d_in[8];
    const float* bg = (const float*)d_in[9];
    const float* Wb = (const float*)d_in[10];
    const float* bb = (const float*)d_in[11];
    const float* We = (const float*)d_in[12];
    float* out = (float*)d_out;

    (void)in_sizes; (void)n_in; (void)out_size;

    size_t sm1 = K1_SMEM_F * sizeof(float);
    size_t sm2 = K2_SMEM_F * sizeof(float);
    cudaFuncSetAttribute(kv_partial_kernel,
                         cudaFuncAttributeMaxDynamicSharedMemorySize, (int)sm1);
    cudaFuncSetAttribute(fused_kernel,
                         cudaFuncAttributeMaxDynamicSharedMemorySize, (int)sm2);

    frag_prep_kernel<<<48, 256>>>(Wq, Wg, Wb, We);
    kv_partial_kernel<<<dim3(NCH, BB), 512, sm1>>>(h_llm, Wk, Wv);
    kv_reduce_kernel<<<(BB * SS * BL) / 256, 256>>>(bk, bv);
    fused_kernel<<<dim3(TT / TOK, NE, BB), 512, sm2>>>(
        h_prime, bq, bg, bb, out);
}

// round 13
// speedup vs baseline: 1.3678x; 1.0688x over previous
#include <cuda_runtime.h>
#include <math.h>
#include <cstdint>

// ---------------- problem constants ----------------
#define BB     8      // batch
#define NE     4      // n_equi
#define TT     1024   // T
#define DD     1024   // D_eq
#define GG     8      // N_GROUP
#define BL     128    // BLOCKS
#define SS     64     // T_text
#define DL     2048   // d_llm
#define SCALE  0.08838834764831843f   // 128^-0.5

#define TOK    16     // tokens per block
#define NCH    32     // kv split chunks
#define KC     64     // d_llm per chunk

// ---------------- scratch (device globals; no allocs allowed) ----------------
__device__ float g_kp[NCH * BB * SS * BL];
__device__ float g_vp[NCH * BB * SS * BL];

// fragment-ordered k/v (pre-tf32 bits).
// g_kf: [b][s_blk 8][kk 16][lane 32] uint2   (scores B operand)
// g_vf: [b][d_blk 16][kk 8][lane 32] uint2   (ctx B operand)
__device__ uint2 g_kf[BB * 8 * 16 * 32];
__device__ uint2 g_vf[BB * 16 * 8 * 32];

// fragment-ordered weights (pre-tf32). wq/wg/wb: [o_blk 16][kk 16][lane 32]
// we: [oc 4][k 16][ntp 2][lane 32] (uint4 packs 2 n-tiles)
__device__ uint2 g_wqf[16 * 16 * 32];
__device__ uint2 g_wgf[16 * 16 * 32];
__device__ uint2 g_wbf[16 * 16 * 32];
__device__ uint4 g_wef[4 * 16 * 2 * 32];

__device__ __forceinline__ uint32_t f2tf32(float x) {
    uint32_t r; asm("cvt.rna.tf32.f32 %0, %1;" : "=r"(r) : "f"(x)); return r;
}

__device__ __forceinline__ void mma_tf32(float d[4], const uint32_t a[4],
                                         const uint32_t b[2]) {
    asm volatile(
        "mma.sync.aligned.m16n8k8.row.col.f32.tf32.tf32.f32 "
        "{%0,%1,%2,%3}, {%4,%5,%6,%7}, {%8,%9}, {%0,%1,%2,%3};"
        : "+f"(d[0]), "+f"(d[1]), "+f"(d[2]), "+f"(d[3])
        : "r"(a[0]), "r"(a[1]), "r"(a[2]), "r"(a[3]),
          "r"(b[0]), "r"(b[1]));
}

// ================= kernel 0: fragment prep =================
__global__ void frag_prep_kernel(const float* __restrict__ Wq,
                                 const float* __restrict__ Wg,
                                 const float* __restrict__ Wb,
                                 const float* __restrict__ We) {
    int idx = blockIdx.x * 256 + threadIdx.x;
    if (idx < 8192) {
        int lane = idx & 31, kk = (idx >> 5) & 15, w = idx >> 9;
        int lr = lane >> 2, lc = lane & 3;
        int ofs = (w * 8 + lr) * 128 + kk * 8 + lc;
        g_wqf[idx] = make_uint2(f2tf32(Wq[ofs]), f2tf32(Wq[ofs + 4]));
        g_wgf[idx] = make_uint2(f2tf32(Wg[ofs]), f2tf32(Wg[ofs + 4]));
        g_wbf[idx] = make_uint2(f2tf32(Wb[ofs]), f2tf32(Wb[ofs + 4]));
    } else if (idx < 8192 + 4096) {
        int j = idx - 8192;
        int lane = j & 31, ntp = (j >> 5) & 1, k = (j >> 6) & 15, oc = j >> 10;
        int lr = lane >> 2, lc = lane & 3;
        int r0 = (oc * 32 + ntp * 16 + lr) * 128 + k * 8 + lc;
        int r1 = r0 + 8 * 128;
        g_wef[j] = make_uint4(f2tf32(We[r0]), f2tf32(We[r0 + 4]),
                              f2tf32(We[r1]), f2tf32(We[r1 + 4]));
    }
}

// ================= kernel 1: k/v projection, 32 chunks =================
#define K1_SMEM_F (SS * KC + 2 * KC * 129)
__global__ __launch_bounds__(512, 2)
void kv_partial_kernel(const float* __restrict__ h_llm,
                       const float* __restrict__ Wk,
                       const float* __restrict__ Wv) {
    extern __shared__ float sm[];
    float* hs  = sm;
    float* wkT = sm + SS * KC;
    float* wvT = wkT + KC * 129;

    const int dc  = blockIdx.x;
    const int b   = blockIdx.y;
    const int tid = threadIdx.x;

    for (int e = tid; e < SS * (KC / 4); e += 512) {
        int s = e >> 4, d4 = e & 15;
        *reinterpret_cast<float4*>(&hs[s * KC + d4 * 4]) =
            *reinterpret_cast<const float4*>(&h_llm[(b * SS + s) * DL + dc * KC + d4 * 4]);
    }
    for (int e = tid; e < BL * (KC / 4); e += 512) {
        int d4 = e & 15, o = e >> 4;
        float4 wk = *reinterpret_cast<const float4*>(&Wk[o * DL + dc * KC + d4 * 4]);
        float4 wv = *reinterpret_cast<const float4*>(&Wv[o * DL + dc * KC + d4 * 4]);
        int d0 = d4 * 4;
        wkT[(d0 + 0) * 129 + o] = wk.x; wkT[(d0 + 1) * 129 + o] = wk.y;
        wkT[(d0 + 2) * 129 + o] = wk.z; wkT[(d0 + 3) * 129 + o] = wk.w;
        wvT[(d0 + 0) * 129 + o] = wv.x; wvT[(d0 + 1) * 129 + o] = wv.y;
        wvT[(d0 + 2) * 129 + o] = wv.z; wvT[(d0 + 3) * 129 + o] = wv.w;
    }
    __syncthreads();

    const int o = tid & 127, qi = tid >> 7;
    for (int st = 0; st < 4; st++) {
        int s0 = qi * 16 + st * 4;
        float ak[4] = {0.f, 0.f, 0.f, 0.f};
        float av[4] = {0.f, 0.f, 0.f, 0.f};
#pragma unroll 4
        for (int d4 = 0; d4 < KC / 4; d4++) {
            float4 h0 = *reinterpret_cast<const float4*>(&hs[(s0 + 0) * KC + d4 * 4]);
            float4 h1 = *reinterpret_cast<const float4*>(&hs[(s0 + 1) * KC + d4 * 4]);
            float4 h2 = *reinterpret_cast<const float4*>(&hs[(s0 + 2) * KC + d4 * 4]);
            float4 h3 = *reinterpret_cast<const float4*>(&hs[(s0 + 3) * KC + d4 * 4]);
            const float hh[4][4] = {{h0.x, h0.y, h0.z, h0.w},
                                    {h1.x, h1.y, h1.z, h1.w},
                                    {h2.x, h2.y, h2.z, h2.w},
                                    {h3.x, h3.y, h3.z, h3.w}};
#pragma unroll
            for (int jd = 0; jd < 4; jd++) {
                float wk = wkT[(d4 * 4 + jd) * 129 + o];
                float wv = wvT[(d4 * 4 + jd) * 129 + o];
#pragma unroll
                for (int j = 0; j < 4; j++) {
                    ak[j] = fmaf(hh[j][jd], wk, ak[j]);
                    av[j] = fmaf(hh[j][jd], wv, av[j]);
                }
            }
        }
#pragma unroll
        for (int j = 0; j < 4; j++) {
            int oidx = ((dc * BB + b) * SS + s0 + j) * BL + o;
            g_kp[oidx] = ak[j];
            g_vp[oidx] = av[j];
        }
    }
}

// ====== kernel 1b: reduce partials + bias -> fragment-ordered k/v ======
__global__ void kv_reduce_kernel(const float* __restrict__ bk,
                                 const float* __restrict__ bv) {
    int idx = blockIdx.x * 256 + threadIdx.x;     // [b][s][o]
    int o = idx & 127;
    int s = (idx >> 7) & 63;
    int b = idx >> 13;
    float sk = bk[o], sv = bv[o];
#pragma unroll
    for (int dc = 0; dc < NCH; dc++) {
        sk += g_kp[dc * (BB * SS * BL) + idx];
        sv += g_vp[dc * (BB * SS * BL) + idx];
    }
    int pos_k = ((b * 8 + (s >> 3)) * 16 + (o >> 3)) * 32 + (s & 7) * 4 + (o & 3);
    reinterpret_cast<uint32_t*>(g_kf)[pos_k * 2 + ((o >> 2) & 1)] = f2tf32(sk);
    int pos_v = ((b * 16 + (o >> 3)) * 8 + (s >> 3)) * 32 + (o & 7) * 4 + (s & 3);
    reinterpret_cast<uint32_t*>(g_vf)[pos_v * 2 + ((s >> 2) & 1)] = f2tf32(sv);
}

// ================= kernel 2: fused, all-mma, 256 thr, 2 CTA/SM ==========
// grid (T/16, n_equi, B), 256 threads (8 warps).
#define HS     1036                       // H row stride (1036 mod 32 == 12)
#define OF_H   0                          // H[m][d] : 16*1036 = 16576
#define OF_INV 16576                      // INV[m][i] stride 132 : 2112 (tf32 bits)
#define OF_AT  (OF_INV + 2112)            // AT[d][m] stride 24 : 3072 (tf32 bits)
#define OF_Q   (OF_AT + 3072)             // Q[m][o] stride 132 : 2112
#define OF_U   (OF_Q + 2112)              // U[m][*] stride 132 : 2112
#define OF_CT  (OF_U + 2112)              // gate[m][o] stride 132 : 2112
#define K2_SMEM_F (OF_CT + 2112)          // 28096 floats = 112384 bytes

__global__ __launch_bounds__(256, 2)
void fused_kernel(const float* __restrict__ h_prime,
                  const float* __restrict__ bq,
                  const float* __restrict__ bg,
                  const float* __restrict__ bb,
                  float* __restrict__ out) {
    extern __shared__ float sm[];
    float* H   = sm + OF_H;    // [m*1036 + d] fp32
    float* INV = sm + OF_INV;  // [m*132 + i] tf32 bits
    float* AT  = sm + OF_AT;   // [d*24 + m] tf32 bits (ctx)
    float* Q   = sm + OF_Q;    // [m*132 + o]
    float* U   = sm + OF_U;    // [m*132 + *]
    float* CT  = sm + OF_CT;   // [m*132 + o] gate fp32

    const int tid = threadIdx.x;
    const int wid = tid >> 5;   // 0..7
    const int l   = tid & 31;
    const int lr  = l >> 2;
    const int lc  = l & 3;
    const int t0  = blockIdx.x * TOK;
    const int n   = blockIdx.y;
    const int b   = blockIdx.z;
    const long long base = ((long long)(b * NE + n) * TT + t0) * DD;

    // ---- phase A: stream h (warp = 2 tokens), store H + group-max -> INV ----
#pragma unroll
    for (int t = 0; t < 2; t++) {
        const int m = wid * 2 + t;
        const float* hrow = h_prime + base + m * DD + l * 4;
        float* Hrow = &H[m * HS + l * 4];
        float4 v0 = *reinterpret_cast<const float4*>(hrow);
        *reinterpret_cast<float4*>(Hrow) = v0;
        float4 mx = v0;
#pragma unroll
        for (int g = 1; g < GG; g++) {
            float4 vg = *reinterpret_cast<const float4*>(hrow + g * 128);
            *reinterpret_cast<float4*>(Hrow + g * 128) = vg;
            mx.x = fmaxf(mx.x, vg.x); mx.y = fmaxf(mx.y, vg.y);
            mx.z = fmaxf(mx.z, vg.z); mx.w = fmaxf(mx.w, vg.w);
        }
        float4 tt;
        tt.x = __uint_as_float(f2tf32(mx.x));
        tt.y = __uint_as_float(f2tf32(mx.y));
        tt.z = __uint_as_float(f2tf32(mx.z));
        tt.w = __uint_as_float(f2tf32(mx.w));
        *reinterpret_cast<float4*>(&INV[m * 132 + l * 4]) = tt;
    }
    __syncthreads();

    // ---- phase C: q = inv @ WqT + bq (mma, 4 warps x n32) -> Q (tf32) ----
    if (wid < 4) {
        float d[4][4];
#pragma unroll
        for (int nb = 0; nb < 4; nb++)
#pragma unroll
            for (int j = 0; j < 4; j++) d[nb][j] = 0.f;
#pragma unroll 4
        for (int kk = 0; kk < 16; kk++) {
            const int i0 = kk * 8;
            uint32_t a[4];
            a[0] = __float_as_uint(INV[lr * 132 + i0 + lc]);
            a[1] = __float_as_uint(INV[(lr + 8) * 132 + i0 + lc]);
            a[2] = __float_as_uint(INV[lr * 132 + i0 + lc + 4]);
            a[3] = __float_as_uint(INV[(lr + 8) * 132 + i0 + lc + 4]);
#pragma unroll
            for (int nb = 0; nb < 4; nb++) {
                uint2 w2 = g_wqf[((wid * 4 + nb) * 16 + kk) * 32 + l];
                uint32_t bf[2] = {w2.x, w2.y};
                mma_tf32(d[nb], a, bf);
            }
        }
#pragma unroll
        for (int nb = 0; nb < 4; nb++) {
            const int o8 = wid * 32 + nb * 8;
            float2 bv2 = *reinterpret_cast<const float2*>(&bq[o8 + lc * 2]);
            Q[lr * 132 + o8 + lc * 2]           = __uint_as_float(f2tf32(d[nb][0] + bv2.x));
            Q[lr * 132 + o8 + lc * 2 + 1]       = __uint_as_float(f2tf32(d[nb][1] + bv2.y));
            Q[(lr + 8) * 132 + o8 + lc * 2]     = __uint_as_float(f2tf32(d[nb][2] + bv2.x));
            Q[(lr + 8) * 132 + o8 + lc * 2 + 1] = __uint_as_float(f2tf32(d[nb][3] + bv2.y));
        }
    }
    __syncthreads();

    // ---- phase D: scores = q.k * SCALE (mma, 4 warps x n16) -> U fp32 ----
    if (wid < 4) {
        float d[2][4];
#pragma unroll
        for (int sb = 0; sb < 2; sb++)
#pragma unroll
            for (int j = 0; j < 4; j++) d[sb][j] = 0.f;
#pragma unroll 4
        for (int kk = 0; kk < 16; kk++) {
            const int i0 = kk * 8;
            uint32_t a[4];
            a[0] = __float_as_uint(Q[lr * 132 + i0 + lc]);
            a[1] = __float_as_uint(Q[(lr + 8) * 132 + i0 + lc]);
            a[2] = __float_as_uint(Q[lr * 132 + i0 + lc + 4]);
            a[3] = __float_as_uint(Q[(lr + 8) * 132 + i0 + lc + 4]);
#pragma unroll
            for (int sb = 0; sb < 2; sb++) {
                uint2 k2 = g_kf[((b * 8 + wid * 2 + sb) * 16 + kk) * 32 + l];
                uint32_t bf[2] = {k2.x, k2.y};
                mma_tf32(d[sb], a, bf);
            }
        }
#pragma unroll
        for (int sb = 0; sb < 2; sb++) {
            const int s8 = wid * 16 + sb * 8;
            U[lr * 132 + s8 + lc * 2]           = d[sb][0] * SCALE;
            U[lr * 132 + s8 + lc * 2 + 1]       = d[sb][1] * SCALE;
            U[(lr + 8) * 132 + s8 + lc * 2]     = d[sb][2] * SCALE;
            U[(lr + 8) * 132 + s8 + lc * 2 + 1] = d[sb][3] * SCALE;
        }
    }
    __syncthreads();

    // ---- phase E: softmax, warp handles 2 rows -> U probs (tf32 bits) ----
#pragma unroll
    for (int rr = 0; rr < 2; rr++) {
        const int row = wid * 2 + rr;
        float x0 = U[row * 132 + l];
        float x1 = U[row * 132 + l + 32];
        float mx = fmaxf(x0, x1);
#pragma unroll
        for (int off = 16; off > 0; off >>= 1)
            mx = fmaxf(mx, __shfl_xor_sync(0xffffffffu, mx, off));
        float e0 = __expf(x0 - mx), e1 = __expf(x1 - mx);
        float s = e0 + e1;
#pragma unroll
        for (int off = 16; off > 0; off >>= 1)
            s += __shfl_xor_sync(0xffffffffu, s, off);
        float inv = 1.f / s;
        U[row * 132 + l]      = __uint_as_float(f2tf32(e0 * inv));
        U[row * 132 + l + 32] = __uint_as_float(f2tf32(e1 * inv));
    }
    __syncthreads();

    // ---- phase F: ctx = attn @ v (mma, 8 warps x n16) -> AT + CT gate ----
    {
        float d[2][4];
#pragma unroll
        for (int db = 0; db < 2; db++)
#pragma unroll
            for (int j = 0; j < 4; j++) d[db][j] = 0.f;
#pragma unroll 4
        for (int kk = 0; kk < 8; kk++) {
            const int i0 = kk * 8;
            uint32_t a[4];
            a[0] = __float_as_uint(U[lr * 132 + i0 + lc]);
            a[1] = __float_as_uint(U[(lr + 8) * 132 + i0 + lc]);
            a[2] = __float_as_uint(U[lr * 132 + i0 + lc + 4]);
            a[3] = __float_as_uint(U[(lr + 8) * 132 + i0 + lc + 4]);
#pragma unroll
            for (int db = 0; db < 2; db++) {
                uint2 v2 = g_vf[((b * 16 + wid * 2 + db) * 8 + kk) * 32 + l];
                uint32_t bf[2] = {v2.x, v2.y};
                mma_tf32(d[db], a, bf);
            }
        }
#pragma unroll
        for (int db = 0; db < 2; db++) {
            const int o8 = wid * 16 + db * 8;
            AT[(o8 + lc * 2) * 24 + lr]         = __uint_as_float(f2tf32(d[db][0]));
            AT[(o8 + lc * 2 + 1) * 24 + lr]     = __uint_as_float(f2tf32(d[db][1]));
            AT[(o8 + lc * 2) * 24 + lr + 8]     = __uint_as_float(f2tf32(d[db][2]));
            AT[(o8 + lc * 2 + 1) * 24 + lr + 8] = __uint_as_float(f2tf32(d[db][3]));
            CT[lr * 132 + o8 + lc * 2]           = 1.f / (1.f + __expf(-d[db][0]));
            CT[lr * 132 + o8 + lc * 2 + 1]       = 1.f / (1.f + __expf(-d[db][1]));
            CT[(lr + 8) * 132 + o8 + lc * 2]     = 1.f / (1.f + __expf(-d[db][2]));
            CT[(lr + 8) * 132 + o8 + lc * 2 + 1] = 1.f / (1.f + __expf(-d[db][3]));
        }
    }
    __syncthreads();

    // ---- phase G: gamma & beta (8 warps x n16), gate folded -> Q, U ----
    {
        float dg[2][4], dbta[2][4];
#pragma unroll
        for (int ob = 0; ob < 2; ob++)
#pragma unroll
            for (int j = 0; j < 4; j++) { dg[ob][j] = 0.f; dbta[ob][j] = 0.f; }
#pragma unroll 4
        for (int kk = 0; kk < 16; kk++) {
            const int i0 = kk * 8;
            uint32_t a[4];
            a[0] = __float_as_uint(AT[(i0 + lc) * 24 + lr]);
            a[1] = __float_as_uint(AT[(i0 + lc) * 24 + lr + 8]);
            a[2] = __float_as_uint(AT[(i0 + lc + 4) * 24 + lr]);
            a[3] = __float_as_uint(AT[(i0 + lc + 4) * 24 + lr + 8]);
#pragma unroll
            for (int ob = 0; ob < 2; ob++) {
                uint2 wg2 = g_wgf[((wid * 2 + ob) * 16 + kk) * 32 + l];
                uint2 wb2 = g_wbf[((wid * 2 + ob) * 16 + kk) * 32 + l];
                uint32_t bG[2] = {wg2.x, wg2.y};
                uint32_t bB[2] = {wb2.x, wb2.y};
                mma_tf32(dg[ob], a, bG);
                mma_tf32(dbta[ob], a, bB);
            }
        }
        __syncthreads();   // CT fully written (phase F) before folding reads
#pragma unroll
        for (int ob = 0; ob < 2; ob++) {
            const int o8 = wid * 16 + ob * 8;
            float2 bgv = *reinterpret_cast<const float2*>(&bg[o8 + lc * 2]);
            float2 bbv = *reinterpret_cast<const float2*>(&bb[o8 + lc * 2]);
            float g00 = CT[lr * 132 + o8 + lc * 2];
            float g01 = CT[lr * 132 + o8 + lc * 2 + 1];
            float g10 = CT[(lr + 8) * 132 + o8 + lc * 2];
            float g11 = CT[(lr + 8) * 132 + o8 + lc * 2 + 1];
            Q[lr * 132 + o8 + lc * 2]           = (dg[ob][0] + bgv.x) * g00;
            Q[lr * 132 + o8 + lc * 2 + 1]       = (dg[ob][1] + bgv.y) * g01;
            Q[(lr + 8) * 132 + o8 + lc * 2]     = (dg[ob][2] + bgv.x) * g10;
            Q[(lr + 8) * 132 + o8 + lc * 2 + 1] = (dg[ob][3] + bgv.y) * g11;
            U[lr * 132 + o8 + lc * 2]           = (dbta[ob][0] + bbv.x) * g00;
            U[lr * 132 + o8 + lc * 2 + 1]       = (dbta[ob][1] + bbv.y) * g01;
            U[(lr + 8) * 132 + o8 + lc * 2]     = (dbta[ob][2] + bbv.x) * g10;
            U[(lr + 8) * 132 + o8 + lc * 2 + 1] = (dbta[ob][3] + bbv.y) * g11;
        }
    }
    __syncthreads();

    // ---- phase J: equi GEMM (8 warps x 64x32 tiles) + epilogue ----
    {
        const int rb = wid >> 2;             // 0..1 (64-row block)
        const int cb = wid & 3;              // 0..3 (32-col block)
        const int o0 = cb * 32;

        float d[4][4][4];
#pragma unroll
        for (int mt = 0; mt < 4; mt++)
#pragma unroll
            for (int nt = 0; nt < 4; nt++)
#pragma unroll
                for (int j = 0; j < 4; j++) d[mt][nt][j] = 0.f;

#pragma unroll 2
        for (int k = 0; k < 16; k++) {
            const int i0 = k * 8;
            uint32_t a[4][4], bfr[4][2];
#pragma unroll
            for (int mt = 0; mt < 4; mt++) {
                const int g = rb * 4 + mt;
                const float* Alo = &H[lr * HS + g * 128 + i0 + lc];
                const float* Ahi = &H[(lr + 8) * HS + g * 128 + i0 + lc];
                a[mt][0] = f2tf32(Alo[0]);
                a[mt][1] = f2tf32(Ahi[0]);
                a[mt][2] = f2tf32(Alo[4]);
                a[mt][3] = f2tf32(Ahi[4]);
            }
            uint4 b01 = g_wef[((cb * 16 + k) * 2 + 0) * 32 + l];
            uint4 b23 = g_wef[((cb * 16 + k) * 2 + 1) * 32 + l];
            bfr[0][0] = b01.x; bfr[0][1] = b01.y;
            bfr[1][0] = b01.z; bfr[1][1] = b01.w;
            bfr[2][0] = b23.x; bfr[2][1] = b23.y;
            bfr[3][0] = b23.z; bfr[3][1] = b23.w;
#pragma unroll
            for (int mt = 0; mt < 4; mt++)
#pragma unroll
                for (int nt = 0; nt < 4; nt++)
                    mma_tf32(d[mt][nt], a[mt], bfr[nt]);
        }

        // epilogue: out = res + gam2*equi + bet2 (gate pre-folded)
#pragma unroll
        for (int mt = 0; mt < 4; mt++) {
            const int g = rb * 4 + mt;
#pragma unroll
            for (int rh = 0; rh < 2; rh++) {
                const int m = lr + rh * 8;
                float* orow = out + base + m * DD + g * 128;
                const float* hrow = &H[m * HS + g * 128];
#pragma unroll
                for (int nt = 0; nt < 4; nt++) {
                    const int o = o0 + nt * 8 + lc * 2;
                    float e0 = d[mt][nt][rh * 2 + 0];
                    float e1 = d[mt][nt][rh * 2 + 1];
                    float2 gam = *reinterpret_cast<const float2*>(&Q[m * 132 + o]);
                    float2 bet = *reinterpret_cast<const float2*>(&U[m * 132 + o]);
                    float2 res = *reinterpret_cast<const float2*>(&hrow[o]);
                    float2 ov;
                    ov.x = res.x + gam.x * e0 + bet.x;
                    ov.y = res.y + gam.y * e1 + bet.y;
                    *reinterpret_cast<float2*>(&orow[o]) = ov;
                }
            }
        }
    }
}

// ================= launcher =================
extern "C" void kernel_launch(void* const* d_in, const int* in_sizes, int n_in,
                              void* d_out, int out_size) {
    const float* h_prime = (const float*)d_in[0];
    const float* h_llm   = (const float*)d_in[1];
    const float* Wq = (const float*)d_in[2];
    const float* bq = (const float*)d_in[3];
    const float* Wk = (const float*)d_in[4];
    const float* bk = (const float*)d_in[5];
    const float* Wv = (const float*)d_in[6];
    const float* bv = (const float*)d_in[7];
    const float* Wg = (const float*)d_in[8];
    const float* bg = (const float*)d_in[9];
    const float* Wb = (const float*)d_in[10];
    const float* bb = (const float*)d_in[11];
    const float* We = (const float*)d_in[12];
    float* out = (float*)d_out;

    (void)in_sizes; (void)n_in; (void)out_size;

    size_t sm1 = K1_SMEM_F * sizeof(float);
    size_t sm2 = K2_SMEM_F * sizeof(float);
    cudaFuncSetAttribute(kv_partial_kernel,
                         cudaFuncAttributeMaxDynamicSharedMemorySize, (int)sm1);
    cudaFuncSetAttribute(fused_kernel,
                         cudaFuncAttributeMaxDynamicSharedMemorySize, (int)sm2);

    frag_prep_kernel<<<48, 256>>>(Wq, Wg, Wb, We);
    kv_partial_kernel<<<dim3(NCH, BB), 512, sm1>>>(h_llm, Wk, Wv);
    kv_reduce_kernel<<<(BB * SS * BL) / 256, 256>>>(bk, bv);
    fused_kernel<<<dim3(TT / TOK, NE, BB), 256, sm2>>>(
        h_prime, bq, bg, bb, out);
}

// round 14
// speedup vs baseline: 1.3827x; 1.0109x over previous
#include <cuda_runtime.h>
#include <math.h>
#include <cstdint>

// ---------------- problem constants ----------------
#define BB     8      // batch
#define NE     4      // n_equi
#define TT     1024   // T
#define DD     1024   // D_eq
#define GG     8      // N_GROUP
#define BL     128    // BLOCKS
#define SS     64     // T_text
#define DL     2048   // d_llm
#define SCALE  0.08838834764831843f   // 128^-0.5

#define TOK    16     // tokens per block
#define NCH    32     // kv split chunks
#define KC     64     // d_llm per chunk

// ---------------- scratch (device globals; no allocs allowed) ----------------
__device__ float g_kp[NCH * BB * SS * BL];
__device__ float g_vp[NCH * BB * SS * BL];

// fragment-ordered k/v (pre-tf32 bits).
__device__ uint2 g_kf[BB * 8 * 16 * 32];
__device__ uint2 g_vf[BB * 16 * 8 * 32];

// fragment-ordered weights (pre-tf32).
__device__ uint2 g_wqf[16 * 16 * 32];
__device__ uint2 g_wgf[16 * 16 * 32];
__device__ uint2 g_wbf[16 * 16 * 32];
__device__ uint4 g_wef[4 * 16 * 2 * 32];

__device__ __forceinline__ uint32_t f2tf32(float x) {
    uint32_t r; asm("cvt.rna.tf32.f32 %0, %1;" : "=r"(r) : "f"(x)); return r;
}

__device__ __forceinline__ void mma_tf32(float d[4], const uint32_t a[4],
                                         const uint32_t b[2]) {
    asm volatile(
        "mma.sync.aligned.m16n8k8.row.col.f32.tf32.tf32.f32 "
        "{%0,%1,%2,%3}, {%4,%5,%6,%7}, {%8,%9}, {%0,%1,%2,%3};"
        : "+f"(d[0]), "+f"(d[1]), "+f"(d[2]), "+f"(d[3])
        : "r"(a[0]), "r"(a[1]), "r"(a[2]), "r"(a[3]),
          "r"(b[0]), "r"(b[1]));
}

#define BAR1() asm volatile("bar.sync 1, 128;" ::: "memory")

// ================= kernel 0: fragment prep =================
__global__ void frag_prep_kernel(const float* __restrict__ Wq,
                                 const float* __restrict__ Wg,
                                 const float* __restrict__ Wb,
                                 const float* __restrict__ We) {
    int idx = blockIdx.x * 256 + threadIdx.x;
    if (idx < 8192) {
        int lane = idx & 31, kk = (idx >> 5) & 15, w = idx >> 9;
        int lr = lane >> 2, lc = lane & 3;
        int ofs = (w * 8 + lr) * 128 + kk * 8 + lc;
        g_wqf[idx] = make_uint2(f2tf32(Wq[ofs]), f2tf32(Wq[ofs + 4]));
        g_wgf[idx] = make_uint2(f2tf32(Wg[ofs]), f2tf32(Wg[ofs + 4]));
        g_wbf[idx] = make_uint2(f2tf32(Wb[ofs]), f2tf32(Wb[ofs + 4]));
    } else if (idx < 8192 + 4096) {
        int j = idx - 8192;
        int lane = j & 31, ntp = (j >> 5) & 1, k = (j >> 6) & 15, oc = j >> 10;
        int lr = lane >> 2, lc = lane & 3;
        int r0 = (oc * 32 + ntp * 16 + lr) * 128 + k * 8 + lc;
        int r1 = r0 + 8 * 128;
        g_wef[j] = make_uint4(f2tf32(We[r0]), f2tf32(We[r0 + 4]),
                              f2tf32(We[r1]), f2tf32(We[r1 + 4]));
    }
}

// ================= kernel 1: k/v projection, 32 chunks =================
#define K1_SMEM_F (SS * KC + 2 * KC * 129)
__global__ __launch_bounds__(512, 2)
void kv_partial_kernel(const float* __restrict__ h_llm,
                       const float* __restrict__ Wk,
                       const float* __restrict__ Wv) {
    extern __shared__ float sm[];
    float* hs  = sm;
    float* wkT = sm + SS * KC;
    float* wvT = wkT + KC * 129;

    const int dc  = blockIdx.x;
    const int b   = blockIdx.y;
    const int tid = threadIdx.x;

    for (int e = tid; e < SS * (KC / 4); e += 512) {
        int s = e >> 4, d4 = e & 15;
        *reinterpret_cast<float4*>(&hs[s * KC + d4 * 4]) =
            *reinterpret_cast<const float4*>(&h_llm[(b * SS + s) * DL + dc * KC + d4 * 4]);
    }
    for (int e = tid; e < BL * (KC / 4); e += 512) {
        int d4 = e & 15, o = e >> 4;
        float4 wk = *reinterpret_cast<const float4*>(&Wk[o * DL + dc * KC + d4 * 4]);
        float4 wv = *reinterpret_cast<const float4*>(&Wv[o * DL + dc * KC + d4 * 4]);
        int d0 = d4 * 4;
        wkT[(d0 + 0) * 129 + o] = wk.x; wkT[(d0 + 1) * 129 + o] = wk.y;
        wkT[(d0 + 2) * 129 + o] = wk.z; wkT[(d0 + 3) * 129 + o] = wk.w;
        wvT[(d0 + 0) * 129 + o] = wv.x; wvT[(d0 + 1) * 129 + o] = wv.y;
        wvT[(d0 + 2) * 129 + o] = wv.z; wvT[(d0 + 3) * 129 + o] = wv.w;
    }
    __syncthreads();

    const int o = tid & 127, qi = tid >> 7;
    for (int st = 0; st < 4; st++) {
        int s0 = qi * 16 + st * 4;
        float ak[4] = {0.f, 0.f, 0.f, 0.f};
        float av[4] = {0.f, 0.f, 0.f, 0.f};
#pragma unroll 4
        for (int d4 = 0; d4 < KC / 4; d4++) {
            float4 h0 = *reinterpret_cast<const float4*>(&hs[(s0 + 0) * KC + d4 * 4]);
            float4 h1 = *reinterpret_cast<const float4*>(&hs[(s0 + 1) * KC + d4 * 4]);
            float4 h2 = *reinterpret_cast<const float4*>(&hs[(s0 + 2) * KC + d4 * 4]);
            float4 h3 = *reinterpret_cast<const float4*>(&hs[(s0 + 3) * KC + d4 * 4]);
            const float hh[4][4] = {{h0.x, h0.y, h0.z, h0.w},
                                    {h1.x, h1.y, h1.z, h1.w},
                                    {h2.x, h2.y, h2.z, h2.w},
                                    {h3.x, h3.y, h3.z, h3.w}};
#pragma unroll
            for (int jd = 0; jd < 4; jd++) {
                float wk = wkT[(d4 * 4 + jd) * 129 + o];
                float wv = wvT[(d4 * 4 + jd) * 129 + o];
#pragma unroll
                for (int j = 0; j < 4; j++) {
                    ak[j] = fmaf(hh[j][jd], wk, ak[j]);
                    av[j] = fmaf(hh[j][jd], wv, av[j]);
                }
            }
        }
#pragma unroll
        for (int j = 0; j < 4; j++) {
            int oidx = ((dc * BB + b) * SS + s0 + j) * BL + o;
            g_kp[oidx] = ak[j];
            g_vp[oidx] = av[j];
        }
    }
}

// ====== kernel 1b: reduce partials + bias -> fragment-ordered k/v ======
__global__ void kv_reduce_kernel(const float* __restrict__ bk,
                                 const float* __restrict__ bv) {
    int idx = blockIdx.x * 256 + threadIdx.x;     // [b][s][o]
    int o = idx & 127;
    int s = (idx >> 7) & 63;
    int b = idx >> 13;
    float sk = bk[o], sv = bv[o];
#pragma unroll
    for (int dc = 0; dc < NCH; dc++) {
        sk += g_kp[dc * (BB * SS * BL) + idx];
        sv += g_vp[dc * (BB * SS * BL) + idx];
    }
    int pos_k = ((b * 8 + (s >> 3)) * 16 + (o >> 3)) * 32 + (s & 7) * 4 + (o & 3);
    reinterpret_cast<uint32_t*>(g_kf)[pos_k * 2 + ((o >> 2) & 1)] = f2tf32(sk);
    int pos_v = ((b * 16 + (o >> 3)) * 8 + (s >> 3)) * 32 + (o & 7) * 4 + (s & 3);
    reinterpret_cast<uint32_t*>(g_vf)[pos_v * 2 + ((s >> 2) & 1)] = f2tf32(sv);
}

// ================= kernel 2: fused, warp-specialized overlap =============
// grid (T/16, n_equi, B), 256 threads (8 warps), 2 CTA/SM.
#define HS     1036                       // H row stride (1036 mod 32 == 12)
#define OF_H   0                          // H[m][d] : 16*1036 = 16576
#define OF_INV 16576                      // INV[m][i] stride 132 : 2112 (tf32 bits)
#define OF_AT  (OF_INV + 2112)            // AT[d][m] stride 24 : 3072 (tf32 bits)
#define OF_Q   (OF_AT + 3072)             // Q[m][o] stride 132 : 2112
#define OF_U   (OF_Q + 2112)              // U[m][*] stride 132 : 2112
#define OF_CT  (OF_U + 2112)              // gate[m][o] stride 132 : 2112
#define K2_SMEM_F (OF_CT + 2112)          // 28096 floats = 112384 bytes

// J mainloop: 64x32 warp tile at rows rb*... (g = rb*4+mt), cols cb*32.
__device__ __forceinline__ void j_mainloop(float (*dJ)[4][4],
                                           const float* __restrict__ H,
                                           int rb, int cb, int lr, int lc, int l) {
#pragma unroll
    for (int mt = 0; mt < 4; mt++)
#pragma unroll
        for (int nt = 0; nt < 4; nt++)
#pragma unroll
            for (int j = 0; j < 4; j++) dJ[mt][nt][j] = 0.f;

#pragma unroll 2
    for (int k = 0; k < 16; k++) {
        const int i0 = k * 8;
        uint32_t a[4][4], bfr[4][2];
#pragma unroll
        for (int mt = 0; mt < 4; mt++) {
            const int g = rb * 4 + mt;
            const float* Alo = &H[lr * HS + g * 128 + i0 + lc];
            const float* Ahi = &H[(lr + 8) * HS + g * 128 + i0 + lc];
            a[mt][0] = f2tf32(Alo[0]);
            a[mt][1] = f2tf32(Ahi[0]);
            a[mt][2] = f2tf32(Alo[4]);
            a[mt][3] = f2tf32(Ahi[4]);
        }
        uint4 b01 = g_wef[((cb * 16 + k) * 2 + 0) * 32 + l];
        uint4 b23 = g_wef[((cb * 16 + k) * 2 + 1) * 32 + l];
        bfr[0][0] = b01.x; bfr[0][1] = b01.y;
        bfr[1][0] = b01.z; bfr[1][1] = b01.w;
        bfr[2][0] = b23.x; bfr[2][1] = b23.y;
        bfr[3][0] = b23.z; bfr[3][1] = b23.w;
#pragma unroll
        for (int mt = 0; mt < 4; mt++)
#pragma unroll
            for (int nt = 0; nt < 4; nt++)
                mma_tf32(dJ[mt][nt], a[mt], bfr[nt]);
    }
}

__global__ __launch_bounds__(256, 2)
void fused_kernel(const float* __restrict__ h_prime,
                  const float* __restrict__ bq,
                  const float* __restrict__ bg,
                  const float* __restrict__ bb,
                  float* __restrict__ out) {
    extern __shared__ float sm[];
    float* H   = sm + OF_H;    // [m*1036 + d] fp32
    float* INV = sm + OF_INV;  // [m*132 + i] tf32 bits
    float* AT  = sm + OF_AT;   // [d*24 + m] tf32 bits (ctx)
    float* Q   = sm + OF_Q;    // [m*132 + o]
    float* U   = sm + OF_U;    // [m*132 + *]
    float* CT  = sm + OF_CT;   // [m*132 + o] gate fp32

    const int tid = threadIdx.x;
    const int wid = tid >> 5;   // 0..7
    const int l   = tid & 31;
    const int lr  = l >> 2;
    const int lc  = l & 3;
    const int t0  = blockIdx.x * TOK;
    const int n   = blockIdx.y;
    const int b   = blockIdx.z;
    const long long base = ((long long)(b * NE + n) * TT + t0) * DD;

    // unified J tile mapping: warps 4-7 -> cols 0-63; warps 0-3 -> cols 64-127
    const int rb = (wid >> 1) & 1;
    const int cb = (wid & 1) + (wid < 4 ? 2 : 0);

    // ---- phase A: stream h (warp = 2 tokens), store H + group-max -> INV ----
#pragma unroll
    for (int t = 0; t < 2; t++) {
        const int m = wid * 2 + t;
        const float* hrow = h_prime + base + m * DD + l * 4;
        float* Hrow = &H[m * HS + l * 4];
        float4 v0 = *reinterpret_cast<const float4*>(hrow);
        *reinterpret_cast<float4*>(Hrow) = v0;
        float4 mx = v0;
#pragma unroll
        for (int g = 1; g < GG; g++) {
            float4 vg = *reinterpret_cast<const float4*>(hrow + g * 128);
            *reinterpret_cast<float4*>(Hrow + g * 128) = vg;
            mx.x = fmaxf(mx.x, vg.x); mx.y = fmaxf(mx.y, vg.y);
            mx.z = fmaxf(mx.z, vg.z); mx.w = fmaxf(mx.w, vg.w);
        }
        float4 tt;
        tt.x = __uint_as_float(f2tf32(mx.x));
        tt.y = __uint_as_float(f2tf32(mx.y));
        tt.z = __uint_as_float(f2tf32(mx.z));
        tt.w = __uint_as_float(f2tf32(mx.w));
        *reinterpret_cast<float4*>(&INV[m * 132 + l * 4]) = tt;
    }
    __syncthreads();

    float dJ[4][4][4];

    if (wid >= 4) {
        // ======== warps 4-7: equi GEMM mainloop, cols 0-63 ========
        j_mainloop(dJ, H, rb, cb, lr, lc, l);
    } else {
        // ======== warps 0-3: attention chain ========
        // ---- phase C: q = inv @ WqT + bq (n32 per warp) -> Q (tf32) ----
        {
            float d[4][4];
#pragma unroll
            for (int nb = 0; nb < 4; nb++)
#pragma unroll
                for (int j = 0; j < 4; j++) d[nb][j] = 0.f;
#pragma unroll 4
            for (int kk = 0; kk < 16; kk++) {
                const int i0 = kk * 8;
                uint32_t a[4];
                a[0] = __float_as_uint(INV[lr * 132 + i0 + lc]);
                a[1] = __float_as_uint(INV[(lr + 8) * 132 + i0 + lc]);
                a[2] = __float_as_uint(INV[lr * 132 + i0 + lc + 4]);
                a[3] = __float_as_uint(INV[(lr + 8) * 132 + i0 + lc + 4]);
#pragma unroll
                for (int nb = 0; nb < 4; nb++) {
                    uint2 w2 = g_wqf[((wid * 4 + nb) * 16 + kk) * 32 + l];
                    uint32_t bf[2] = {w2.x, w2.y};
                    mma_tf32(d[nb], a, bf);
                }
            }
#pragma unroll
            for (int nb = 0; nb < 4; nb++) {
                const int o8 = wid * 32 + nb * 8;
                float2 bv2 = *reinterpret_cast<const float2*>(&bq[o8 + lc * 2]);
                Q[lr * 132 + o8 + lc * 2]           = __uint_as_float(f2tf32(d[nb][0] + bv2.x));
                Q[lr * 132 + o8 + lc * 2 + 1]       = __uint_as_float(f2tf32(d[nb][1] + bv2.y));
                Q[(lr + 8) * 132 + o8 + lc * 2]     = __uint_as_float(f2tf32(d[nb][2] + bv2.x));
                Q[(lr + 8) * 132 + o8 + lc * 2 + 1] = __uint_as_float(f2tf32(d[nb][3] + bv2.y));
            }
        }
        BAR1();

        // ---- phase D: scores = q.k * SCALE (n16 per warp) -> U fp32 ----
        {
            float d[2][4];
#pragma unroll
            for (int sb = 0; sb < 2; sb++)
#pragma unroll
                for (int j = 0; j < 4; j++) d[sb][j] = 0.f;
#pragma unroll 4
            for (int kk = 0; kk < 16; kk++) {
                const int i0 = kk * 8;
                uint32_t a[4];
                a[0] = __float_as_uint(Q[lr * 132 + i0 + lc]);
                a[1] = __float_as_uint(Q[(lr + 8) * 132 + i0 + lc]);
                a[2] = __float_as_uint(Q[lr * 132 + i0 + lc + 4]);
                a[3] = __float_as_uint(Q[(lr + 8) * 132 + i0 + lc + 4]);
#pragma unroll
                for (int sb = 0; sb < 2; sb++) {
                    uint2 k2 = g_kf[((b * 8 + wid * 2 + sb) * 16 + kk) * 32 + l];
                    uint32_t bf[2] = {k2.x, k2.y};
                    mma_tf32(d[sb], a, bf);
                }
            }
#pragma unroll
            for (int sb = 0; sb < 2; sb++) {
                const int s8 = wid * 16 + sb * 8;
                U[lr * 132 + s8 + lc * 2]           = d[sb][0] * SCALE;
                U[lr * 132 + s8 + lc * 2 + 1]       = d[sb][1] * SCALE;
                U[(lr + 8) * 132 + s8 + lc * 2]     = d[sb][2] * SCALE;
                U[(lr + 8) * 132 + s8 + lc * 2 + 1] = d[sb][3] * SCALE;
            }
        }
        BAR1();

        // ---- phase E: softmax, warp handles 4 rows -> U probs (tf32) ----
#pragma unroll
        for (int rr = 0; rr < 4; rr++) {
            const int row = wid * 4 + rr;
            float x0 = U[row * 132 + l];
            float x1 = U[row * 132 + l + 32];
            float mx = fmaxf(x0, x1);
#pragma unroll
            for (int off = 16; off > 0; off >>= 1)
                mx = fmaxf(mx, __shfl_xor_sync(0xffffffffu, mx, off));
            float e0 = __expf(x0 - mx), e1 = __expf(x1 - mx);
            float s = e0 + e1;
#pragma unroll
            for (int off = 16; off > 0; off >>= 1)
                s += __shfl_xor_sync(0xffffffffu, s, off);
            float inv = 1.f / s;
            U[row * 132 + l]      = __uint_as_float(f2tf32(e0 * inv));
            U[row * 132 + l + 32] = __uint_as_float(f2tf32(e1 * inv));
        }
        BAR1();

        // ---- phase F: ctx = attn @ v (n32 per warp) -> AT + CT gate ----
        {
            float d[4][4];
#pragma unroll
            for (int db = 0; db < 4; db++)
#pragma unroll
                for (int j = 0; j < 4; j++) d[db][j] = 0.f;
#pragma unroll 4
            for (int kk = 0; kk < 8; kk++) {
                const int i0 = kk * 8;
                uint32_t a[4];
                a[0] = __float_as_uint(U[lr * 132 + i0 + lc]);
                a[1] = __float_as_uint(U[(lr + 8) * 132 + i0 + lc]);
                a[2] = __float_as_uint(U[lr * 132 + i0 + lc + 4]);
                a[3] = __float_as_uint(U[(lr + 8) * 132 + i0 + lc + 4]);
#pragma unroll
                for (int db = 0; db < 4; db++) {
                    uint2 v2 = g_vf[((b * 16 + wid * 4 + db) * 8 + kk) * 32 + l];
                    uint32_t bf[2] = {v2.x, v2.y};
                    mma_tf32(d[db], a, bf);
                }
            }
#pragma unroll
            for (int db = 0; db < 4; db++) {
                const int o8 = wid * 32 + db * 8;
                AT[(o8 + lc * 2) * 24 + lr]         = __uint_as_float(f2tf32(d[db][0]));
                AT[(o8 + lc * 2 + 1) * 24 + lr]     = __uint_as_float(f2tf32(d[db][1]));
                AT[(o8 + lc * 2) * 24 + lr + 8]     = __uint_as_float(f2tf32(d[db][2]));
                AT[(o8 + lc * 2 + 1) * 24 + lr + 8] = __uint_as_float(f2tf32(d[db][3]));
                CT[lr * 132 + o8 + lc * 2]           = 1.f / (1.f + __expf(-d[db][0]));
                CT[lr * 132 + o8 + lc * 2 + 1]       = 1.f / (1.f + __expf(-d[db][1]));
                CT[(lr + 8) * 132 + o8 + lc * 2]     = 1.f / (1.f + __expf(-d[db][2]));
                CT[(lr + 8) * 132 + o8 + lc * 2 + 1] = 1.f / (1.f + __expf(-d[db][3]));
            }
        }
        BAR1();

        // ---- phase G: gamma & beta (4 ob per warp), gate folded -> Q, U ----
        {
            float dg[4][4], dbta[4][4];
#pragma unroll
            for (int ob = 0; ob < 4; ob++)
#pragma unroll
                for (int j = 0; j < 4; j++) { dg[ob][j] = 0.f; dbta[ob][j] = 0.f; }
#pragma unroll 4
            for (int kk = 0; kk < 16; kk++) {
                const int i0 = kk * 8;
                uint32_t a[4];
                a[0] = __float_as_uint(AT[(i0 + lc) * 24 + lr]);
                a[1] = __float_as_uint(AT[(i0 + lc) * 24 + lr + 8]);
                a[2] = __float_as_uint(AT[(i0 + lc + 4) * 24 + lr]);
                a[3] = __float_as_uint(AT[(i0 + lc + 4) * 24 + lr + 8]);
#pragma unroll
                for (int ob = 0; ob < 4; ob++) {
                    uint2 wg2 = g_wgf[((wid * 4 + ob) * 16 + kk) * 32 + l];
                    uint2 wb2 = g_wbf[((wid * 4 + ob) * 16 + kk) * 32 + l];
                    uint32_t bG[2] = {wg2.x, wg2.y};
                    uint32_t bB[2] = {wb2.x, wb2.y};
                    mma_tf32(dg[ob], a, bG);
                    mma_tf32(dbta[ob], a, bB);
                }
            }
#pragma unroll
            for (int ob = 0; ob < 4; ob++) {
                const int o8 = wid * 32 + ob * 8;
                float2 bgv = *reinterpret_cast<const float2*>(&bg[o8 + lc * 2]);
                float2 bbv = *reinterpret_cast<const float2*>(&bb[o8 + lc * 2]);
                float g00 = CT[lr * 132 + o8 + lc * 2];
                float g01 = CT[lr * 132 + o8 + lc * 2 + 1];
                float g10 = CT[(lr + 8) * 132 + o8 + lc * 2];
                float g11 = CT[(lr + 8) * 132 + o8 + lc * 2 + 1];
                Q[lr * 132 + o8 + lc * 2]           = (dg[ob][0] + bgv.x) * g00;
                Q[lr * 132 + o8 + lc * 2 + 1]       = (dg[ob][1] + bgv.y) * g01;
                Q[(lr + 8) * 132 + o8 + lc * 2]     = (dg[ob][2] + bgv.x) * g10;
                Q[(lr + 8) * 132 + o8 + lc * 2 + 1] = (dg[ob][3] + bgv.y) * g11;
                U[lr * 132 + o8 + lc * 2]           = (dbta[ob][0] + bbv.x) * g00;
                U[lr * 132 + o8 + lc * 2 + 1]       = (dbta[ob][1] + bbv.y) * g01;
                U[(lr + 8) * 132 + o8 + lc * 2]     = (dbta[ob][2] + bbv.x) * g10;
                U[(lr + 8) * 132 + o8 + lc * 2 + 1] = (dbta[ob][3] + bbv.y) * g11;
            }
        }
    }

    __syncthreads();   // join: gamma2/beta2 complete; J-left accums ready

    if (wid < 4) {
        // warps 0-3 now do their J half (cols 64-127)
        j_mainloop(dJ, H, rb, cb, lr, lc, l);
    }

    // ---- epilogue (per-warp region): out = res + gam2*equi + bet2 ----
    {
        const int o0 = cb * 32;
#pragma unroll
        for (int mt = 0; mt < 4; mt++) {
            const int g = rb * 4 + mt;
#pragma unroll
            for (int rh = 0; rh < 2; rh++) {
                const int m = lr + rh * 8;
                float* orow = out + base + m * DD + g * 128;
                const float* hrow = &H[m * HS + g * 128];
#pragma unroll
                for (int nt = 0; nt < 4; nt++) {
                    const int o = o0 + nt * 8 + lc * 2;
                    float e0 = dJ[mt][nt][rh * 2 + 0];
                    float e1 = dJ[mt][nt][rh * 2 + 1];
                    float2 gam = *reinterpret_cast<const float2*>(&Q[m * 132 + o]);
                    float2 bet = *reinterpret_cast<const float2*>(&U[m * 132 + o]);
                    float2 res = *reinterpret_cast<const float2*>(&hrow[o]);
                    float2 ov;
                    ov.x = res.x + gam.x * e0 + bet.x;
                    ov.y = res.y + gam.y * e1 + bet.y;
                    *reinterpret_cast<float2*>(&orow[o]) = ov;
                }
            }
        }
    }
}

// ================= launcher =================
extern "C" void kernel_launch(void* const* d_in, const int* in_sizes, int n_in,
                              void* d_out, int out_size) {
    const float* h_prime = (const float*)d_in[0];
    const float* h_llm   = (const float*)d_in[1];
    const float* Wq = (const float*)d_in[2];
    const float* bq = (const float*)d_in[3];
    const float* Wk = (const float*)d_in[4];
    const float* bk = (const float*)d_in[5];
    const float* Wv = (const float*)d_in[6];
    const float* bv = (const float*)d_in[7];
    const float* Wg = (const float*)d_in[8];
    const float* bg = (const float*)d_in[9];
    const float* Wb = (const float*)d_in[10];
    const float* bb = (const float*)d_in[11];
    const float* We = (const float*)d_in[12];
    float* out = (float*)d_out;

    (void)in_sizes; (void)n_in; (void)out_size;

    size_t sm1 = K1_SMEM_F * sizeof(float);
    size_t sm2 = K2_SMEM_F * sizeof(float);
    cudaFuncSetAttribute(kv_partial_kernel,
                         cudaFuncAttributeMaxDynamicSharedMemorySize, (int)sm1);
    cudaFuncSetAttribute(fused_kernel,
                         cudaFuncAttributeMaxDynamicSharedMemorySize, (int)sm2);

    frag_prep_kernel<<<48, 256>>>(Wq, Wg, Wb, We);
    kv_partial_kernel<<<dim3(NCH, BB), 512, sm1>>>(h_llm, Wk, Wv);
    kv_reduce_kernel<<<(BB * SS * BL) / 256, 256>>>(bk, bv);
    fused_kernel<<<dim3(TT / TOK, NE, BB), 256, sm2>>>(
        h_prime, bq, bg, bb, out);
}